// round 6
// baseline (speedup 1.0000x reference)
#include <cuda_runtime.h>
#include <math.h>

#define N_NODES 100000
#define N_EDGES 1600000
#define FDIM 128
#define N_GRAPHS 100
#define N_CLASSES 10
#define BN_EPS 1e-5f
#define SCAN_CHUNK 1024
#define NB_SCAN ((N_NODES + SCAN_CHUNK - 1) / SCAN_CHUNK)   // 98
#define POOL_CHUNK 256
#define NB_POOL ((N_NODES + POOL_CHUNK - 1) / POOL_CHUNK)

// ------------------------- scratch (static device globals) -------------------
__device__ float g_bufA[(size_t)N_NODES * FDIM];   // h = x @ W
__device__ float g_bufB[(size_t)N_NODES * FDIM];   // agg / normalized x
__device__ float g_dis[N_NODES];                   // deg^{-1/2}
__device__ int   g_hist[N_NODES];
__device__ int   g_rowptr[N_NODES + 1];
__device__ int   g_cursor[N_NODES];
__device__ int   g_csr_src[N_EDGES];
__device__ float g_csr_w[N_EDGES];                 // dis[src] per CSR slot
__device__ int   g_part[NB_SCAN + 1];
__device__ float g_bnsum[3 * FDIM];
__device__ float g_bnsq[3 * FDIM];
__device__ float g_pool[N_GRAPHS * FDIM];
__device__ float g_cnt[N_GRAPHS];

// ------------------------------ init / zero ----------------------------------
__global__ void zero_kernel() {
    int i = blockIdx.x * blockDim.x + threadIdx.x;
    int stride = gridDim.x * blockDim.x;
    for (int j = i; j < N_NODES; j += stride) g_hist[j] = 0;
    for (int j = i; j < N_GRAPHS * FDIM; j += stride) g_pool[j] = 0.f;
    for (int j = i; j < N_GRAPHS; j += stride) g_cnt[j] = 0.f;
    for (int j = i; j < 3 * FDIM; j += stride) { g_bnsum[j] = 0.f; g_bnsq[j] = 0.f; }
}

__global__ void hist_kernel(const int* __restrict__ dst) {
    int e = blockIdx.x * blockDim.x + threadIdx.x;
    if (e < N_EDGES) atomicAdd(&g_hist[dst[e]], 1);
}

__global__ void dis_kernel() {
    int n = blockIdx.x * blockDim.x + threadIdx.x;
    if (n < N_NODES) g_dis[n] = rsqrtf((float)g_hist[n] + 1.0f);
}

// ------------------------------ scan (rowptr) --------------------------------
__global__ void scanA_kernel() {
    __shared__ int s[SCAN_CHUNK];
    int t = threadIdx.x;
    int idx = blockIdx.x * SCAN_CHUNK + t;
    s[t] = (idx < N_NODES) ? g_hist[idx] : 0;
    __syncthreads();
    for (int o = SCAN_CHUNK / 2; o > 0; o >>= 1) {
        if (t < o) s[t] += s[t + o];
        __syncthreads();
    }
    if (t == 0) g_part[blockIdx.x] = s[0];
}

__global__ void scanB_kernel() {
    // tiny: single thread exclusive-scans the 98 block sums
    int run = 0;
    for (int b = 0; b < NB_SCAN; b++) {
        int v = g_part[b];
        g_part[b] = run;
        run += v;
    }
}

__global__ void scanC_kernel() {
    __shared__ int s[SCAN_CHUNK];
    int t = threadIdx.x;
    int idx = blockIdx.x * SCAN_CHUNK + t;
    int v = (idx < N_NODES) ? g_hist[idx] : 0;
    s[t] = v;
    __syncthreads();
    for (int o = 1; o < SCAN_CHUNK; o <<= 1) {
        int a = (t >= o) ? s[t - o] : 0;
        __syncthreads();
        s[t] += a;
        __syncthreads();
    }
    if (idx < N_NODES) {
        int excl = g_part[blockIdx.x] + s[t] - v;   // exclusive prefix
        g_rowptr[idx] = excl;
        g_cursor[idx] = excl;
        if (idx == N_NODES - 1) g_rowptr[N_NODES] = excl + v;
    }
}

__global__ void fill_kernel(const int* __restrict__ src, const int* __restrict__ dst) {
    int e = blockIdx.x * blockDim.x + threadIdx.x;
    if (e < N_EDGES) {
        int s = src[e], d = dst[e];
        int pos = atomicAdd(&g_cursor[d], 1);
        g_csr_src[pos] = s;
        g_csr_w[pos] = g_dis[s];
    }
}

// --------------------------------- GEMM --------------------------------------
// H(g_bufA) = X @ W ; X = external input (layer 0) or g_bufB (layers 1,2).
// block = 128 threads (one per output col), 64 rows per block.
// W fully staged in smem (64KB) + 64-row X tile (32KB) => 96KB dynamic smem.
// Inner loop uses packed fma.rn.f32x2 to double fp32 FMA throughput.
__global__ void gemm_kernel(const float* __restrict__ Xext, const float* __restrict__ W) {
    extern __shared__ float sm[];
    float* sW = sm;             // 128*128
    float* sX = sm + 16384;     // 64*128
    const float* X = (Xext != nullptr) ? Xext : g_bufB;
    int c = threadIdx.x;
    for (int i = c; i < 128 * 128; i += 128) sW[i] = W[i];
    int row0 = blockIdx.x * 64;
    int nr = N_NODES - row0; if (nr > 64) nr = 64;   // always a multiple of 8
    for (int i = c; i < nr * 128; i += 128) sX[i] = X[(size_t)row0 * 128 + i];
    __syncthreads();

    for (int r0 = 0; r0 < nr; r0 += 8) {
        unsigned long long acc[8];
#pragma unroll
        for (int i = 0; i < 8; i++) acc[i] = 0ull;   // packed {0.f, 0.f}
        for (int k = 0; k < 128; k += 2) {
            float w0 = sW[k * 128 + c];
            float w1 = sW[(k + 1) * 128 + c];
            unsigned long long wp;
            asm("mov.b64 %0,{%1,%2};" : "=l"(wp) : "f"(w0), "f"(w1));
#pragma unroll
            for (int i = 0; i < 8; i++) {
                unsigned long long xp =
                    *reinterpret_cast<const unsigned long long*>(&sX[(r0 + i) * 128 + k]);
                asm("fma.rn.f32x2 %0,%1,%2,%0;" : "+l"(acc[i]) : "l"(xp), "l"(wp));
            }
        }
#pragma unroll
        for (int i = 0; i < 8; i++) {
            float lo, hi;
            asm("mov.b64 {%0,%1},%2;" : "=f"(lo), "=f"(hi) : "l"(acc[i]));
            g_bufA[(size_t)(row0 + r0 + i) * 128 + c] = lo + hi;
        }
    }
}

// ------------------------------- SpMM gather ---------------------------------
// agg[n] = sum_{e: dst=n} h[src]*dis[src]*dis[n] + h[n]*dis[n]^2 + b
// one warp per node; lane l owns cols [4l,4l+4). No float atomics anywhere.
__global__ void spmm_kernel(const float* __restrict__ bias) {
    int gtid = blockIdx.x * blockDim.x + threadIdx.x;
    int warp = gtid >> 5;
    int lane = threadIdx.x & 31;
    int nwarps = (gridDim.x * blockDim.x) >> 5;
    float4 bv = reinterpret_cast<const float4*>(bias)[lane];

    for (int n = warp; n < N_NODES; n += nwarps) {
        float dn = g_dis[n];
        float sl = dn * dn;
        float4 hs = *reinterpret_cast<const float4*>(&g_bufA[(size_t)n * 128 + lane * 4]);
        float4 acc;
        acc.x = hs.x * sl + bv.x;
        acc.y = hs.y * sl + bv.y;
        acc.z = hs.z * sl + bv.z;
        acc.w = hs.w * sl + bv.w;

        int s0 = g_rowptr[n], s1 = g_rowptr[n + 1];
        for (int base = s0; base < s1; base += 32) {
            int j = base + lane;
            int sj = 0; float wj = 0.f;
            if (j < s1) { sj = g_csr_src[j]; wj = g_csr_w[j] * dn; }
            int cnt = s1 - base; if (cnt > 32) cnt = 32;
            for (int t = 0; t < cnt; t++) {
                int s = __shfl_sync(0xffffffffu, sj, t);
                float w = __shfl_sync(0xffffffffu, wj, t);
                float4 hv = *reinterpret_cast<const float4*>(&g_bufA[(size_t)s * 128 + lane * 4]);
                acc.x += hv.x * w;
                acc.y += hv.y * w;
                acc.z += hv.z * w;
                acc.w += hv.w * w;
            }
        }
        *reinterpret_cast<float4*>(&g_bufB[(size_t)n * 128 + lane * 4]) = acc;
    }
}

// --------------------------------- BatchNorm ---------------------------------
__global__ void bn_stats_kernel(int layer) {
    int c = threadIdx.x;
    float s = 0.f, q = 0.f;
    for (int r = blockIdx.x; r < N_NODES; r += gridDim.x) {
        float v = g_bufB[(size_t)r * 128 + c];
        s += v;
        q += v * v;
    }
    atomicAdd(&g_bnsum[layer * FDIM + c], s);
    atomicAdd(&g_bnsq[layer * FDIM + c], q);
}

__global__ void bn_apply_kernel(int layer, const float* __restrict__ gamma,
                                const float* __restrict__ beta) {
    int c = threadIdx.x;
    float invN = 1.0f / (float)N_NODES;
    float mean = g_bnsum[layer * FDIM + c] * invN;
    float var = g_bnsq[layer * FDIM + c] * invN - mean * mean;
    float scale = rsqrtf(var + BN_EPS) * gamma[c];
    float shift = beta[c] - mean * scale;
    for (int r = blockIdx.x; r < N_NODES; r += gridDim.x) {
        float v = g_bufB[(size_t)r * 128 + c];
        g_bufB[(size_t)r * 128 + c] = fmaxf(v * scale + shift, 0.f);
    }
}

// ---------------------------------- Pool -------------------------------------
// batch is sorted: each block run-length accumulates a contiguous node chunk.
__global__ void pool_kernel(const int* __restrict__ batch) {
    int c = threadIdx.x;
    int start = blockIdx.x * POOL_CHUNK;
    int end = start + POOL_CHUNK; if (end > N_NODES) end = N_NODES;
    if (start >= end) return;
    float acc = 0.f;
    int cur = batch[start];
    int cnt = 0;
    for (int r = start; r < end; r++) {
        int g = batch[r];
        if (g != cur) {
            atomicAdd(&g_pool[cur * FDIM + c], acc);
            if (c == 0) atomicAdd(&g_cnt[cur], (float)cnt);
            acc = 0.f; cnt = 0; cur = g;
        }
        acc += g_bufB[(size_t)r * 128 + c];
        cnt++;
    }
    atomicAdd(&g_pool[cur * FDIM + c], acc);
    if (c == 0) atomicAdd(&g_cnt[cur], (float)cnt);
}

// -------------------------------- Classifier ---------------------------------
__global__ void classify_kernel(const float* __restrict__ lw1, const float* __restrict__ lb1,
                                const float* __restrict__ lw2, const float* __restrict__ lb2,
                                float* __restrict__ out) {
    __shared__ float p[FDIM], h[FDIM], lo[N_CLASSES];
    int g = blockIdx.x;
    int c = threadIdx.x;
    float cv = fmaxf(g_cnt[g], 1.0f);
    p[c] = g_pool[g * FDIM + c] / cv;
    __syncthreads();
    float a = lb1[c];
    for (int k = 0; k < FDIM; k++) a += p[k] * lw1[k * FDIM + c];
    h[c] = fmaxf(a, 0.f);
    __syncthreads();
    if (c < N_CLASSES) {
        float a2 = lb2[c];
        for (int k = 0; k < FDIM; k++) a2 += h[k] * lw2[k * N_CLASSES + c];
        lo[c] = a2;
    }
    __syncthreads();
    if (c == 0) {
        float m = lo[0];
        for (int j = 1; j < N_CLASSES; j++) m = fmaxf(m, lo[j]);
        float s = 0.f;
        for (int j = 0; j < N_CLASSES; j++) s += expf(lo[j] - m);
        float L = m + logf(s);
        for (int j = 0; j < N_CLASSES; j++) out[g * N_CLASSES + j] = lo[j] - L;
    }
}

// --------------------------------- launch ------------------------------------
extern "C" void kernel_launch(void* const* d_in, const int* in_sizes, int n_in,
                              void* d_out, int out_size) {
    const float* x = (const float*)d_in[0];
    const int* ei = (const int*)d_in[1];
    const int* src = ei;
    const int* dst = ei + N_EDGES;
    const int* batch = (const int*)d_in[2];
    const float* W[3]     = { (const float*)d_in[3], (const float*)d_in[7],  (const float*)d_in[11] };
    const float* b[3]     = { (const float*)d_in[4], (const float*)d_in[8],  (const float*)d_in[12] };
    const float* gamma[3] = { (const float*)d_in[5], (const float*)d_in[9],  (const float*)d_in[13] };
    const float* beta[3]  = { (const float*)d_in[6], (const float*)d_in[10], (const float*)d_in[14] };
    const float* lin1_w = (const float*)d_in[15];
    const float* lin1_b = (const float*)d_in[16];
    const float* lin2_w = (const float*)d_in[17];
    const float* lin2_b = (const float*)d_in[18];
    float* out = (float*)d_out;

    cudaFuncSetAttribute(gemm_kernel, cudaFuncAttributeMaxDynamicSharedMemorySize, 98304);

    // graph preprocessing (every call: must be deterministic & self-contained)
    zero_kernel<<<224, 256>>>();
    hist_kernel<<<(N_EDGES + 255) / 256, 256>>>(dst);
    dis_kernel<<<(N_NODES + 255) / 256, 256>>>();
    scanA_kernel<<<NB_SCAN, SCAN_CHUNK>>>();
    scanB_kernel<<<1, 1>>>();
    scanC_kernel<<<NB_SCAN, SCAN_CHUNK>>>();
    fill_kernel<<<(N_EDGES + 255) / 256, 256>>>(src, dst);

    int gemm_blocks = (N_NODES + 63) / 64;
    const float* cur = x;
    for (int l = 0; l < 3; l++) {
        gemm_kernel<<<gemm_blocks, 128, 98304>>>(cur, W[l]);
        spmm_kernel<<<1184, 256>>>(b[l]);
        bn_stats_kernel<<<592, 128>>>(l);
        bn_apply_kernel<<<1024, 128>>>(l, gamma[l], beta[l]);
        cur = nullptr;   // gemm reads g_bufB for layers 1,2
    }

    pool_kernel<<<NB_POOL, 128>>>(batch);
    classify_kernel<<<N_GRAPHS, 128>>>(lin1_w, lin1_b, lin2_w, lin2_b, out);
}

// round 7
// speedup vs baseline: 1.2486x; 1.2486x over previous
#include <cuda_runtime.h>
#include <math.h>

#define N_NODES 100000
#define N_EDGES 1600000
#define FDIM 128
#define N_GRAPHS 100
#define N_CLASSES 10
#define BN_EPS 1e-5f
#define SCAN_THREADS 1024
#define NB_SCAN ((N_NODES + SCAN_THREADS - 1) / SCAN_THREADS)   // 98
#define POOL_CHUNK 256
#define NB_POOL ((N_NODES + POOL_CHUNK - 1) / POOL_CHUNK)

typedef unsigned long long ull;

// ------------------------- scratch (static device globals) -------------------
__device__ float g_bufA[(size_t)N_NODES * FDIM];   // h = x @ W
__device__ float g_bufB[(size_t)N_NODES * FDIM];   // agg (pre-BN)
__device__ float g_dis[N_NODES];                   // deg^{-1/2}
__device__ int   g_hist[N_NODES];
__device__ int   g_rowptr[N_NODES + 1];
__device__ int   g_cursor[N_NODES];
__device__ int   g_csr_src[N_EDGES];
__device__ float g_csr_w[N_EDGES];                 // dis[src] per CSR slot
__device__ float g_bnsum[3 * FDIM];
__device__ float g_bnsq[3 * FDIM];
__device__ float g_pool[N_GRAPHS * FDIM];
__device__ float g_cnt[N_GRAPHS];

// ------------------------------ init / zero ----------------------------------
__global__ void zero_kernel() {
    int i = blockIdx.x * blockDim.x + threadIdx.x;
    int stride = gridDim.x * blockDim.x;
    for (int j = i; j < N_NODES; j += stride) g_hist[j] = 0;
    for (int j = i; j < N_GRAPHS * FDIM; j += stride) g_pool[j] = 0.f;
    for (int j = i; j < N_GRAPHS; j += stride) g_cnt[j] = 0.f;
    for (int j = i; j < 3 * FDIM; j += stride) { g_bnsum[j] = 0.f; g_bnsq[j] = 0.f; }
}

__global__ void hist_kernel(const int* __restrict__ dst) {
    int e = blockIdx.x * blockDim.x + threadIdx.x;
    if (e < N_EDGES) atomicAdd(&g_hist[dst[e]], 1);
}

// ------------------ fused scan (rowptr + cursor + dis), 1 block --------------
__global__ void scan_fused_kernel() {
    __shared__ int swt[32];
    __shared__ int s_carry;
    int t = threadIdx.x;
    int lane = t & 31;
    int w = t >> 5;
    if (t == 0) s_carry = 0;
    __syncthreads();

    for (int chunk = 0; chunk < NB_SCAN; chunk++) {
        int idx = chunk * SCAN_THREADS + t;
        int v = (idx < N_NODES) ? g_hist[idx] : 0;
        // warp inclusive scan
        int s = v;
#pragma unroll
        for (int o = 1; o < 32; o <<= 1) {
            int n = __shfl_up_sync(0xffffffffu, s, o);
            if (lane >= o) s += n;
        }
        if (lane == 31) swt[w] = s;
        __syncthreads();
        if (w == 0) {
            int ws = swt[lane];
#pragma unroll
            for (int o = 1; o < 32; o <<= 1) {
                int n = __shfl_up_sync(0xffffffffu, ws, o);
                if (lane >= o) ws += n;
            }
            swt[lane] = ws;
        }
        __syncthreads();
        int incl = s + ((w > 0) ? swt[w - 1] : 0);
        int base = s_carry;
        int excl = base + incl - v;
        if (idx < N_NODES) {
            g_rowptr[idx] = excl;
            g_cursor[idx] = excl;
            g_dis[idx] = rsqrtf((float)v + 1.0f);
        }
        __syncthreads();
        if (t == SCAN_THREADS - 1) s_carry = base + incl;
        __syncthreads();
    }
    if (t == 0) g_rowptr[N_NODES] = s_carry;
}

__global__ void fill_kernel(const int* __restrict__ src, const int* __restrict__ dst) {
    int e = blockIdx.x * blockDim.x + threadIdx.x;
    if (e < N_EDGES) {
        int s = src[e], d = dst[e];
        int pos = atomicAdd(&g_cursor[d], 1);
        g_csr_src[pos] = s;
        g_csr_w[pos] = g_dis[s];
    }
}

// --------------------------------- GEMM --------------------------------------
// H(g_bufA) = relu(BN(X)) @ W  (BN fused into X-load for layers 1,2; bnLayer=-1
// disables it for layer 0). Block = 128 threads; each thread owns 2 output
// columns (c, c+64) x 8 rows; 64 rows/block; 96KB smem (W 64KB + X tile 32KB),
// 2 CTAs/SM. Inner loop: 16 FFMA2 per ~30 instr => FMA-pipe-bound.
__global__ void gemm_kernel(const float* __restrict__ Xext, const float* __restrict__ W,
                            int bnLayer, const float* __restrict__ gamma,
                            const float* __restrict__ beta) {
    extern __shared__ float sm[];
    float* sW = sm;             // 128*128
    float* sX = sm + 16384;     // 64*128
    const float* X = (Xext != nullptr) ? Xext : g_bufB;
    int tid = threadIdx.x;

    float myScale = 1.f, myShift = 0.f;
    if (bnLayer >= 0) {
        float invN = 1.0f / (float)N_NODES;
        float mean = g_bnsum[bnLayer * FDIM + tid] * invN;
        float var = g_bnsq[bnLayer * FDIM + tid] * invN - mean * mean;
        myScale = rsqrtf(var + BN_EPS) * gamma[tid];
        myShift = beta[tid] - mean * myScale;
    }

    for (int i = tid; i < 128 * 128; i += 128) sW[i] = W[i];
    int row0 = blockIdx.x * 64;
    int nr = N_NODES - row0; if (nr > 64) nr = 64;   // 64 or 32 (both mult of 16)
    for (int j = 0; j < nr; j++) {                   // column = tid for every j
        float v = X[(size_t)(row0 + j) * 128 + tid];
        if (bnLayer >= 0) v = fmaxf(v * myScale + myShift, 0.f);
        sX[j * 128 + tid] = v;
    }
    __syncthreads();

    int c = tid & 63;            // owns cols c and c+64
    int rbase = (tid >> 6) * 8;  // row sub-group 0..7 or 8..15

    for (int g = 0; g < nr; g += 16) {
        ull acc[16];
#pragma unroll
        for (int i = 0; i < 16; i++) acc[i] = 0ull;
#pragma unroll 2
        for (int k = 0; k < 128; k += 2) {
            float w00 = sW[k * 128 + c];
            float w10 = sW[(k + 1) * 128 + c];
            float w01 = sW[k * 128 + c + 64];
            float w11 = sW[(k + 1) * 128 + c + 64];
            ull wp0, wp1;
            asm("mov.b64 %0,{%1,%2};" : "=l"(wp0) : "f"(w00), "f"(w10));
            asm("mov.b64 %0,{%1,%2};" : "=l"(wp1) : "f"(w01), "f"(w11));
#pragma unroll
            for (int i = 0; i < 8; i++) {
                ull xp = *reinterpret_cast<const ull*>(&sX[(g + rbase + i) * 128 + k]);
                asm("fma.rn.f32x2 %0,%1,%2,%0;" : "+l"(acc[2 * i]) : "l"(xp), "l"(wp0));
                asm("fma.rn.f32x2 %0,%1,%2,%0;" : "+l"(acc[2 * i + 1]) : "l"(xp), "l"(wp1));
            }
        }
#pragma unroll
        for (int i = 0; i < 8; i++) {
            int row = row0 + g + rbase + i;
            float lo, hi;
            asm("mov.b64 {%0,%1},%2;" : "=f"(lo), "=f"(hi) : "l"(acc[2 * i]));
            g_bufA[(size_t)row * 128 + c] = lo + hi;
            asm("mov.b64 {%0,%1},%2;" : "=f"(lo), "=f"(hi) : "l"(acc[2 * i + 1]));
            g_bufA[(size_t)row * 128 + c + 64] = lo + hi;
        }
    }
}

// ------------------------------- SpMM gather ---------------------------------
// bufB[n] = sum_{e: dst=n} h[src]*dis[src]*dis[n] + h[n]*dis[n]^2 + b
// One warp per node; lane l owns cols [4l,4l+4). BN column stats (sum, sumsq)
// are accumulated per-lane in registers and block-reduced at the end.
__global__ void spmm_kernel(const float* __restrict__ bias, int layer) {
    __shared__ float sred[8 * 128];   // 8 warps x 128 cols (reused twice)
    int gtid = blockIdx.x * blockDim.x + threadIdx.x;
    int warp = gtid >> 5;
    int wloc = threadIdx.x >> 5;
    int lane = threadIdx.x & 31;
    int nwarps = (gridDim.x * blockDim.x) >> 5;
    float4 bv = reinterpret_cast<const float4*>(bias)[lane];

    float4 ps = make_float4(0.f, 0.f, 0.f, 0.f);
    float4 pq = make_float4(0.f, 0.f, 0.f, 0.f);

    for (int n = warp; n < N_NODES; n += nwarps) {
        float dn = g_dis[n];
        float sl = dn * dn;
        float4 hs = *reinterpret_cast<const float4*>(&g_bufA[(size_t)n * 128 + lane * 4]);
        float4 acc;
        acc.x = hs.x * sl + bv.x;
        acc.y = hs.y * sl + bv.y;
        acc.z = hs.z * sl + bv.z;
        acc.w = hs.w * sl + bv.w;

        int s0 = g_rowptr[n], s1 = g_rowptr[n + 1];
        for (int base = s0; base < s1; base += 32) {
            int j = base + lane;
            int sj = 0; float wj = 0.f;
            if (j < s1) { sj = g_csr_src[j]; wj = g_csr_w[j] * dn; }
            int cnt = s1 - base; if (cnt > 32) cnt = 32;
            for (int t = 0; t < cnt; t++) {
                int s = __shfl_sync(0xffffffffu, sj, t);
                float w = __shfl_sync(0xffffffffu, wj, t);
                float4 hv = *reinterpret_cast<const float4*>(&g_bufA[(size_t)s * 128 + lane * 4]);
                acc.x += hv.x * w;
                acc.y += hv.y * w;
                acc.z += hv.z * w;
                acc.w += hv.w * w;
            }
        }
        *reinterpret_cast<float4*>(&g_bufB[(size_t)n * 128 + lane * 4]) = acc;

        ps.x += acc.x; ps.y += acc.y; ps.z += acc.z; ps.w += acc.w;
        pq.x += acc.x * acc.x; pq.y += acc.y * acc.y;
        pq.z += acc.z * acc.z; pq.w += acc.w * acc.w;
    }

    // block reduction of BN partials (lanes own disjoint columns)
    float4* s4 = reinterpret_cast<float4*>(sred);
    s4[wloc * 32 + lane] = ps;
    __syncthreads();
    if (threadIdx.x < 128) {
        float tsum = 0.f;
        for (int ww = 0; ww < 8; ww++) tsum += sred[ww * 128 + threadIdx.x];
        atomicAdd(&g_bnsum[layer * FDIM + threadIdx.x], tsum);
    }
    __syncthreads();
    s4[wloc * 32 + lane] = pq;
    __syncthreads();
    if (threadIdx.x < 128) {
        float tsq = 0.f;
        for (int ww = 0; ww < 8; ww++) tsq += sred[ww * 128 + threadIdx.x];
        atomicAdd(&g_bnsq[layer * FDIM + threadIdx.x], tsq);
    }
}

// ---------------------------------- Pool -------------------------------------
// Applies layer-2 BN + ReLU on the fly. batch is sorted: run-length accumulate.
__global__ void pool_kernel(const int* __restrict__ batch,
                            const float* __restrict__ gamma,
                            const float* __restrict__ beta) {
    int c = threadIdx.x;
    float invN = 1.0f / (float)N_NODES;
    float mean = g_bnsum[2 * FDIM + c] * invN;
    float var = g_bnsq[2 * FDIM + c] * invN - mean * mean;
    float scale = rsqrtf(var + BN_EPS) * gamma[c];
    float shift = beta[c] - mean * scale;

    int start = blockIdx.x * POOL_CHUNK;
    int end = start + POOL_CHUNK; if (end > N_NODES) end = N_NODES;
    if (start >= end) return;
    float acc = 0.f;
    int cur = batch[start];
    int cnt = 0;
    for (int r = start; r < end; r++) {
        int g = batch[r];
        if (g != cur) {
            atomicAdd(&g_pool[cur * FDIM + c], acc);
            if (c == 0) atomicAdd(&g_cnt[cur], (float)cnt);
            acc = 0.f; cnt = 0; cur = g;
        }
        float v = g_bufB[(size_t)r * 128 + c];
        acc += fmaxf(v * scale + shift, 0.f);
        cnt++;
    }
    atomicAdd(&g_pool[cur * FDIM + c], acc);
    if (c == 0) atomicAdd(&g_cnt[cur], (float)cnt);
}

// -------------------------------- Classifier ---------------------------------
__global__ void classify_kernel(const float* __restrict__ lw1, const float* __restrict__ lb1,
                                const float* __restrict__ lw2, const float* __restrict__ lb2,
                                float* __restrict__ out) {
    __shared__ float p[FDIM], h[FDIM], lo[N_CLASSES];
    int g = blockIdx.x;
    int c = threadIdx.x;
    float cv = fmaxf(g_cnt[g], 1.0f);
    p[c] = g_pool[g * FDIM + c] / cv;
    __syncthreads();
    float a = lb1[c];
    for (int k = 0; k < FDIM; k++) a += p[k] * lw1[k * FDIM + c];
    h[c] = fmaxf(a, 0.f);
    __syncthreads();
    if (c < N_CLASSES) {
        float a2 = lb2[c];
        for (int k = 0; k < FDIM; k++) a2 += h[k] * lw2[k * N_CLASSES + c];
        lo[c] = a2;
    }
    __syncthreads();
    if (c == 0) {
        float m = lo[0];
        for (int j = 1; j < N_CLASSES; j++) m = fmaxf(m, lo[j]);
        float s = 0.f;
        for (int j = 0; j < N_CLASSES; j++) s += expf(lo[j] - m);
        float L = m + logf(s);
        for (int j = 0; j < N_CLASSES; j++) out[g * N_CLASSES + j] = lo[j] - L;
    }
}

// --------------------------------- launch ------------------------------------
extern "C" void kernel_launch(void* const* d_in, const int* in_sizes, int n_in,
                              void* d_out, int out_size) {
    const float* x = (const float*)d_in[0];
    const int* ei = (const int*)d_in[1];
    const int* src = ei;
    const int* dst = ei + N_EDGES;
    const int* batch = (const int*)d_in[2];
    const float* W[3]     = { (const float*)d_in[3], (const float*)d_in[7],  (const float*)d_in[11] };
    const float* b[3]     = { (const float*)d_in[4], (const float*)d_in[8],  (const float*)d_in[12] };
    const float* gamma[3] = { (const float*)d_in[5], (const float*)d_in[9],  (const float*)d_in[13] };
    const float* beta[3]  = { (const float*)d_in[6], (const float*)d_in[10], (const float*)d_in[14] };
    const float* lin1_w = (const float*)d_in[15];
    const float* lin1_b = (const float*)d_in[16];
    const float* lin2_w = (const float*)d_in[17];
    const float* lin2_b = (const float*)d_in[18];
    float* out = (float*)d_out;

    cudaFuncSetAttribute(gemm_kernel, cudaFuncAttributeMaxDynamicSharedMemorySize, 98304);

    int gemm_blocks = (N_NODES + 63) / 64;

    // Launch order positions gemm0 at index 3 and spmm0 at index 5 so the
    // ncu capture window (-s 5 -c 1) lands on a heavy kernel.
    zero_kernel<<<224, 256>>>();                                     // 0
    hist_kernel<<<(N_EDGES + 255) / 256, 256>>>(dst);                // 1
    scan_fused_kernel<<<1, SCAN_THREADS>>>();                        // 2
    gemm_kernel<<<gemm_blocks, 128, 98304>>>(x, W[0], -1, nullptr, nullptr);  // 3
    fill_kernel<<<(N_EDGES + 255) / 256, 256>>>(src, dst);           // 4
    spmm_kernel<<<1184, 256>>>(b[0], 0);                             // 5
    gemm_kernel<<<gemm_blocks, 128, 98304>>>(nullptr, W[1], 0, gamma[0], beta[0]); // 6
    spmm_kernel<<<1184, 256>>>(b[1], 1);                             // 7
    gemm_kernel<<<gemm_blocks, 128, 98304>>>(nullptr, W[2], 1, gamma[1], beta[1]); // 8
    spmm_kernel<<<1184, 256>>>(b[2], 2);                             // 9
    pool_kernel<<<NB_POOL, 128>>>(batch, gamma[2], beta[2]);         // 10
    classify_kernel<<<N_GRAPHS, 128>>>(lin1_w, lin1_b, lin2_w, lin2_b, out); // 11
}

// round 8
// speedup vs baseline: 1.6814x; 1.3466x over previous
#include <cuda_runtime.h>
#include <math.h>

#define N_NODES 100000
#define N_EDGES 1600000
#define FDIM 128
#define N_GRAPHS 100
#define N_CLASSES 10
#define BN_EPS 1e-5f
#define SCAN_THREADS 1024
#define NB_SCAN ((N_NODES + SCAN_THREADS - 1) / SCAN_THREADS)   // 98
#define POOL_CHUNK 256
#define NB_POOL ((N_NODES + POOL_CHUNK - 1) / POOL_CHUNK)

typedef unsigned long long ull;

// ------------------------- scratch (static device globals) -------------------
__device__ float g_bufA[(size_t)N_NODES * FDIM];   // h = x @ W
__device__ float g_bufB[(size_t)N_NODES * FDIM];   // agg (pre-BN)
__device__ float g_dis[N_NODES];                   // deg^{-1/2}
__device__ int   g_hist[N_NODES];
__device__ int   g_rowptr[N_NODES + 1];
__device__ int   g_cursor[N_NODES];
__device__ int   g_csr_src[N_EDGES];
__device__ float g_csr_w[N_EDGES];                 // dis[src] per CSR slot
__device__ float g_bnsum[3 * FDIM];
__device__ float g_bnsq[3 * FDIM];
__device__ float g_pool[N_GRAPHS * FDIM];
__device__ float g_cnt[N_GRAPHS];

// ------------------------------ init / zero ----------------------------------
__global__ void zero_kernel() {
    int i = blockIdx.x * blockDim.x + threadIdx.x;
    int stride = gridDim.x * blockDim.x;
    for (int j = i; j < N_NODES; j += stride) g_hist[j] = 0;
    for (int j = i; j < N_GRAPHS * FDIM; j += stride) g_pool[j] = 0.f;
    for (int j = i; j < N_GRAPHS; j += stride) g_cnt[j] = 0.f;
    for (int j = i; j < 3 * FDIM; j += stride) { g_bnsum[j] = 0.f; g_bnsq[j] = 0.f; }
}

__global__ void hist_kernel(const int* __restrict__ dst) {
    int e = blockIdx.x * blockDim.x + threadIdx.x;
    if (e < N_EDGES) atomicAdd(&g_hist[dst[e]], 1);
}

// ------------------ fused scan (rowptr + cursor + dis), 1 block --------------
__global__ void scan_fused_kernel() {
    __shared__ int swt[32];
    __shared__ int s_carry;
    int t = threadIdx.x;
    int lane = t & 31;
    int w = t >> 5;
    if (t == 0) s_carry = 0;
    __syncthreads();

    for (int chunk = 0; chunk < NB_SCAN; chunk++) {
        int idx = chunk * SCAN_THREADS + t;
        int v = (idx < N_NODES) ? g_hist[idx] : 0;
        int s = v;
#pragma unroll
        for (int o = 1; o < 32; o <<= 1) {
            int n = __shfl_up_sync(0xffffffffu, s, o);
            if (lane >= o) s += n;
        }
        if (lane == 31) swt[w] = s;
        __syncthreads();
        if (w == 0) {
            int ws = swt[lane];
#pragma unroll
            for (int o = 1; o < 32; o <<= 1) {
                int n = __shfl_up_sync(0xffffffffu, ws, o);
                if (lane >= o) ws += n;
            }
            swt[lane] = ws;
        }
        __syncthreads();
        int incl = s + ((w > 0) ? swt[w - 1] : 0);
        int base = s_carry;
        int excl = base + incl - v;
        if (idx < N_NODES) {
            g_rowptr[idx] = excl;
            g_cursor[idx] = excl;
            g_dis[idx] = rsqrtf((float)v + 1.0f);
        }
        __syncthreads();
        if (t == SCAN_THREADS - 1) s_carry = base + incl;
        __syncthreads();
    }
    if (t == 0) g_rowptr[N_NODES] = s_carry;
}

__global__ void fill_kernel(const int* __restrict__ src, const int* __restrict__ dst) {
    int e = blockIdx.x * blockDim.x + threadIdx.x;
    if (e < N_EDGES) {
        int s = src[e], d = dst[e];
        int pos = atomicAdd(&g_cursor[d], 1);
        g_csr_src[pos] = s;
        g_csr_w[pos] = g_dis[s];
    }
}

// --------------------------------- GEMM --------------------------------------
// H(g_bufA) = relu(BN(X)) @ W  (BN fused into X-load; bnLayer=-1 disables).
// 256 threads/CTA, 64 rows/CTA, W (64KB) + X tile (32KB) = 96KB smem.
// 2 CTAs/SM => 32 warps/SM (occ 50%) to hide LDS latency.
// Thread owns 2 cols (c, c+64) x 16 rows; acc packed over k-pairs (FFMA2).
__global__ __launch_bounds__(256, 2)
void gemm_kernel(const float* __restrict__ Xext, const float* __restrict__ W,
                 int bnLayer, const float* __restrict__ gamma,
                 const float* __restrict__ beta) {
    extern __shared__ float sm[];
    float* sW = sm;             // 128*128
    float* sX = sm + 16384;     // 64*128
    const float* X = (Xext != nullptr) ? Xext : g_bufB;
    int tid = threadIdx.x;
    int scol = tid & 127;       // staging column (also BN column)
    int srow = tid >> 7;        // staging row offset (0/1)

    float myScale = 1.f, myShift = 0.f;
    if (bnLayer >= 0) {
        float invN = 1.0f / (float)N_NODES;
        float mean = g_bnsum[bnLayer * FDIM + scol] * invN;
        float var = g_bnsq[bnLayer * FDIM + scol] * invN - mean * mean;
        myScale = rsqrtf(var + BN_EPS) * gamma[scol];
        myShift = beta[scol] - mean * myScale;
    }

    for (int i = tid; i < 128 * 128; i += 256) sW[i] = W[i];
    int row0 = blockIdx.x * 64;
    int nr = N_NODES - row0; if (nr > 64) nr = 64;   // 64 or 32 (mult of 16)
    for (int j = srow; j < nr; j += 2) {             // 2 rows per pass
        float v = X[(size_t)(row0 + j) * 128 + scol];
        if (bnLayer >= 0) v = fmaxf(v * myScale + myShift, 0.f);
        sX[j * 128 + scol] = v;
    }
    __syncthreads();

    int c = tid & 63;                 // owns cols c and c+64
    int rbase = (tid >> 6) * 16;      // 16 rows per thread

    ull acc[32];
#pragma unroll
    for (int i = 0; i < 32; i++) acc[i] = 0ull;

#pragma unroll 2
    for (int k = 0; k < 128; k += 2) {
        float w00 = sW[k * 128 + c];
        float w10 = sW[(k + 1) * 128 + c];
        float w01 = sW[k * 128 + c + 64];
        float w11 = sW[(k + 1) * 128 + c + 64];
        ull wp0, wp1;
        asm("mov.b64 %0,{%1,%2};" : "=l"(wp0) : "f"(w00), "f"(w10));
        asm("mov.b64 %0,{%1,%2};" : "=l"(wp1) : "f"(w01), "f"(w11));
#pragma unroll
        for (int i = 0; i < 16; i++) {
            ull xp = *reinterpret_cast<const ull*>(&sX[(rbase + i) * 128 + k]);
            asm("fma.rn.f32x2 %0,%1,%2,%0;" : "+l"(acc[2 * i]) : "l"(xp), "l"(wp0));
            asm("fma.rn.f32x2 %0,%1,%2,%0;" : "+l"(acc[2 * i + 1]) : "l"(xp), "l"(wp1));
        }
    }

    if (rbase < nr) {                 // nr is a multiple of 16
#pragma unroll
        for (int i = 0; i < 16; i++) {
            int row = row0 + rbase + i;
            float lo, hi;
            asm("mov.b64 {%0,%1},%2;" : "=f"(lo), "=f"(hi) : "l"(acc[2 * i]));
            g_bufA[(size_t)row * 128 + c] = lo + hi;
            asm("mov.b64 {%0,%1},%2;" : "=f"(lo), "=f"(hi) : "l"(acc[2 * i + 1]));
            g_bufA[(size_t)row * 128 + c + 64] = lo + hi;
        }
    }
}

// ------------------------------- SpMM gather ---------------------------------
// bufB[n] = sum_{e: dst=n} h[src]*dis[src]*dis[n] + h[n]*dis[n]^2 + b
// One warp per node; lane l owns cols [4l,4l+4). BN column stats fused.
__global__ void spmm_kernel(const float* __restrict__ bias, int layer) {
    __shared__ float sred[8 * 128];
    int gtid = blockIdx.x * blockDim.x + threadIdx.x;
    int warp = gtid >> 5;
    int wloc = threadIdx.x >> 5;
    int lane = threadIdx.x & 31;
    int nwarps = (gridDim.x * blockDim.x) >> 5;
    float4 bv = reinterpret_cast<const float4*>(bias)[lane];

    float4 ps = make_float4(0.f, 0.f, 0.f, 0.f);
    float4 pq = make_float4(0.f, 0.f, 0.f, 0.f);

    for (int n = warp; n < N_NODES; n += nwarps) {
        float dn = g_dis[n];
        float sl = dn * dn;
        float4 hs = *reinterpret_cast<const float4*>(&g_bufA[(size_t)n * 128 + lane * 4]);
        float4 acc;
        acc.x = hs.x * sl + bv.x;
        acc.y = hs.y * sl + bv.y;
        acc.z = hs.z * sl + bv.z;
        acc.w = hs.w * sl + bv.w;

        int s0 = g_rowptr[n], s1 = g_rowptr[n + 1];
        for (int base = s0; base < s1; base += 32) {
            int j = base + lane;
            int sj = 0; float wj = 0.f;
            if (j < s1) { sj = g_csr_src[j]; wj = g_csr_w[j] * dn; }
            int cnt = s1 - base; if (cnt > 32) cnt = 32;
            for (int t = 0; t < cnt; t++) {
                int s = __shfl_sync(0xffffffffu, sj, t);
                float w = __shfl_sync(0xffffffffu, wj, t);
                float4 hv = *reinterpret_cast<const float4*>(&g_bufA[(size_t)s * 128 + lane * 4]);
                acc.x += hv.x * w;
                acc.y += hv.y * w;
                acc.z += hv.z * w;
                acc.w += hv.w * w;
            }
        }
        *reinterpret_cast<float4*>(&g_bufB[(size_t)n * 128 + lane * 4]) = acc;

        ps.x += acc.x; ps.y += acc.y; ps.z += acc.z; ps.w += acc.w;
        pq.x += acc.x * acc.x; pq.y += acc.y * acc.y;
        pq.z += acc.z * acc.z; pq.w += acc.w * acc.w;
    }

    float4* s4 = reinterpret_cast<float4*>(sred);
    s4[wloc * 32 + lane] = ps;
    __syncthreads();
    if (threadIdx.x < 128) {
        float tsum = 0.f;
        for (int ww = 0; ww < 8; ww++) tsum += sred[ww * 128 + threadIdx.x];
        atomicAdd(&g_bnsum[layer * FDIM + threadIdx.x], tsum);
    }
    __syncthreads();
    s4[wloc * 32 + lane] = pq;
    __syncthreads();
    if (threadIdx.x < 128) {
        float tsq = 0.f;
        for (int ww = 0; ww < 8; ww++) tsq += sred[ww * 128 + threadIdx.x];
        atomicAdd(&g_bnsq[layer * FDIM + threadIdx.x], tsq);
    }
}

// ---------------------------------- Pool -------------------------------------
__global__ void pool_kernel(const int* __restrict__ batch,
                            const float* __restrict__ gamma,
                            const float* __restrict__ beta) {
    int c = threadIdx.x;
    float invN = 1.0f / (float)N_NODES;
    float mean = g_bnsum[2 * FDIM + c] * invN;
    float var = g_bnsq[2 * FDIM + c] * invN - mean * mean;
    float scale = rsqrtf(var + BN_EPS) * gamma[c];
    float shift = beta[c] - mean * scale;

    int start = blockIdx.x * POOL_CHUNK;
    int end = start + POOL_CHUNK; if (end > N_NODES) end = N_NODES;
    if (start >= end) return;
    float acc = 0.f;
    int cur = batch[start];
    int cnt = 0;
    for (int r = start; r < end; r++) {
        int g = batch[r];
        if (g != cur) {
            atomicAdd(&g_pool[cur * FDIM + c], acc);
            if (c == 0) atomicAdd(&g_cnt[cur], (float)cnt);
            acc = 0.f; cnt = 0; cur = g;
        }
        float v = g_bufB[(size_t)r * 128 + c];
        acc += fmaxf(v * scale + shift, 0.f);
        cnt++;
    }
    atomicAdd(&g_pool[cur * FDIM + c], acc);
    if (c == 0) atomicAdd(&g_cnt[cur], (float)cnt);
}

// -------------------------------- Classifier ---------------------------------
__global__ void classify_kernel(const float* __restrict__ lw1, const float* __restrict__ lb1,
                                const float* __restrict__ lw2, const float* __restrict__ lb2,
                                float* __restrict__ out) {
    __shared__ float p[FDIM], h[FDIM], lo[N_CLASSES];
    int g = blockIdx.x;
    int c = threadIdx.x;
    float cv = fmaxf(g_cnt[g], 1.0f);
    p[c] = g_pool[g * FDIM + c] / cv;
    __syncthreads();
    float a = lb1[c];
    for (int k = 0; k < FDIM; k++) a += p[k] * lw1[k * FDIM + c];
    h[c] = fmaxf(a, 0.f);
    __syncthreads();
    if (c < N_CLASSES) {
        float a2 = lb2[c];
        for (int k = 0; k < FDIM; k++) a2 += h[k] * lw2[k * N_CLASSES + c];
        lo[c] = a2;
    }
    __syncthreads();
    if (c == 0) {
        float m = lo[0];
        for (int j = 1; j < N_CLASSES; j++) m = fmaxf(m, lo[j]);
        float s = 0.f;
        for (int j = 0; j < N_CLASSES; j++) s += expf(lo[j] - m);
        float L = m + logf(s);
        for (int j = 0; j < N_CLASSES; j++) out[g * N_CLASSES + j] = lo[j] - L;
    }
}

// --------------------------------- launch ------------------------------------
extern "C" void kernel_launch(void* const* d_in, const int* in_sizes, int n_in,
                              void* d_out, int out_size) {
    const float* x = (const float*)d_in[0];
    const int* ei = (const int*)d_in[1];
    const int* src = ei;
    const int* dst = ei + N_EDGES;
    const int* batch = (const int*)d_in[2];
    const float* W[3]     = { (const float*)d_in[3], (const float*)d_in[7],  (const float*)d_in[11] };
    const float* b[3]     = { (const float*)d_in[4], (const float*)d_in[8],  (const float*)d_in[12] };
    const float* gamma[3] = { (const float*)d_in[5], (const float*)d_in[9],  (const float*)d_in[13] };
    const float* beta[3]  = { (const float*)d_in[6], (const float*)d_in[10], (const float*)d_in[14] };
    const float* lin1_w = (const float*)d_in[15];
    const float* lin1_b = (const float*)d_in[16];
    const float* lin2_w = (const float*)d_in[17];
    const float* lin2_b = (const float*)d_in[18];
    float* out = (float*)d_out;

    cudaFuncSetAttribute(gemm_kernel, cudaFuncAttributeMaxDynamicSharedMemorySize, 98304);

    int gemm_blocks = (N_NODES + 63) / 64;

    // Launch order keeps gemm0 at index 3 and spmm0 at index 5 (ncu -s 5 -c 1).
    zero_kernel<<<224, 256>>>();                                     // 0
    hist_kernel<<<(N_EDGES + 255) / 256, 256>>>(dst);                // 1
    scan_fused_kernel<<<1, SCAN_THREADS>>>();                        // 2
    gemm_kernel<<<gemm_blocks, 256, 98304>>>(x, W[0], -1, nullptr, nullptr);  // 3
    fill_kernel<<<(N_EDGES + 255) / 256, 256>>>(src, dst);           // 4
    spmm_kernel<<<1184, 256>>>(b[0], 0);                             // 5
    gemm_kernel<<<gemm_blocks, 256, 98304>>>(nullptr, W[1], 0, gamma[0], beta[0]); // 6
    spmm_kernel<<<1184, 256>>>(b[1], 1);                             // 7
    gemm_kernel<<<gemm_blocks, 256, 98304>>>(nullptr, W[2], 1, gamma[1], beta[1]); // 8
    spmm_kernel<<<1184, 256>>>(b[2], 2);                             // 9
    pool_kernel<<<NB_POOL, 128>>>(batch, gamma[2], beta[2]);         // 10
    classify_kernel<<<N_GRAPHS, 128>>>(lin1_w, lin1_b, lin2_w, lin2_b, out); // 11
}

// round 11
// speedup vs baseline: 1.6890x; 1.0045x over previous
#include <cuda_runtime.h>
#include <math.h>

#define N_NODES 100000
#define N_EDGES 1600000
#define FDIM 128
#define N_GRAPHS 100
#define N_CLASSES 10
#define BN_EPS 1e-5f
#define SCAN_THREADS 1024
#define NB_SCAN ((N_NODES + SCAN_THREADS - 1) / SCAN_THREADS)   // 98
#define POOL_CHUNK 256
#define NB_POOL ((N_NODES + POOL_CHUNK - 1) / POOL_CHUNK)

typedef unsigned long long ull;

// ------------------------- scratch (static device globals) -------------------
__device__ float g_bufA[(size_t)N_NODES * FDIM];   // h = x @ W
__device__ float g_bufB[(size_t)N_NODES * FDIM];   // agg (pre-BN)
__device__ float g_dis[N_NODES];                   // deg^{-1/2}
__device__ int   g_hist[N_NODES];
__device__ int   g_rowptr[N_NODES + 1];
__device__ int   g_cursor[N_NODES];
__device__ int2  g_csrp[N_EDGES];                  // {src, bitcast(dis[src])}
__device__ float g_bnsum[3 * FDIM];
__device__ float g_bnsq[3 * FDIM];
__device__ float g_pool[N_GRAPHS * FDIM];
__device__ float g_cnt[N_GRAPHS];

// ------------------------------ init / zero ----------------------------------
__global__ void zero_kernel() {
    int i = blockIdx.x * blockDim.x + threadIdx.x;
    int stride = gridDim.x * blockDim.x;
    for (int j = i; j < N_NODES; j += stride) g_hist[j] = 0;
    for (int j = i; j < N_GRAPHS * FDIM; j += stride) g_pool[j] = 0.f;
    for (int j = i; j < N_GRAPHS; j += stride) g_cnt[j] = 0.f;
    for (int j = i; j < 3 * FDIM; j += stride) { g_bnsum[j] = 0.f; g_bnsq[j] = 0.f; }
}

__global__ void hist_kernel(const int* __restrict__ dst) {
    int e = blockIdx.x * blockDim.x + threadIdx.x;
    if (e < N_EDGES) atomicAdd(&g_hist[dst[e]], 1);
}

// ------------------ fused scan (rowptr + cursor + dis), 1 block --------------
__global__ void scan_fused_kernel() {
    __shared__ int swt[32];
    __shared__ int s_carry;
    int t = threadIdx.x;
    int lane = t & 31;
    int w = t >> 5;
    if (t == 0) s_carry = 0;
    __syncthreads();

    for (int chunk = 0; chunk < NB_SCAN; chunk++) {
        int idx = chunk * SCAN_THREADS + t;
        int v = (idx < N_NODES) ? g_hist[idx] : 0;
        int s = v;
#pragma unroll
        for (int o = 1; o < 32; o <<= 1) {
            int n = __shfl_up_sync(0xffffffffu, s, o);
            if (lane >= o) s += n;
        }
        if (lane == 31) swt[w] = s;
        __syncthreads();
        if (w == 0) {
            int ws = swt[lane];
#pragma unroll
            for (int o = 1; o < 32; o <<= 1) {
                int n = __shfl_up_sync(0xffffffffu, ws, o);
                if (lane >= o) ws += n;
            }
            swt[lane] = ws;
        }
        __syncthreads();
        int incl = s + ((w > 0) ? swt[w - 1] : 0);
        int base = s_carry;
        int excl = base + incl - v;
        if (idx < N_NODES) {
            g_rowptr[idx] = excl;
            g_cursor[idx] = excl;
            g_dis[idx] = rsqrtf((float)v + 1.0f);
        }
        __syncthreads();
        if (t == SCAN_THREADS - 1) s_carry = base + incl;
        __syncthreads();
    }
    if (t == 0) g_rowptr[N_NODES] = s_carry;
}

__global__ void fill_kernel(const int* __restrict__ src, const int* __restrict__ dst) {
    int e = blockIdx.x * blockDim.x + threadIdx.x;
    if (e < N_EDGES) {
        int s = src[e], d = dst[e];
        int pos = atomicAdd(&g_cursor[d], 1);
        g_csrp[pos] = make_int2(s, __float_as_int(g_dis[s]));
    }
}

// --------------------------------- GEMM --------------------------------------
// H(g_bufA) = relu(BN(X)) @ W  (BN fused into X-load; bnLayer=-1 disables).
// 256 threads/CTA, 64 rows/CTA. Smem: W transposed to c-major with XOR swizzle
// (chunk = kq ^ (c&7)) -> conflict-free LDS.128; X row-major, read as LDS.128
// broadcast (all lanes of a warp share the row). Thread owns 2 cols x 16 rows.
// Per k-quad per warp: 18 LDS.128 + 64 FFMA2 (78% fma density).
__global__ __launch_bounds__(256, 2)
void gemm_kernel(const float* __restrict__ Xext, const float* __restrict__ W,
                 int bnLayer, const float* __restrict__ gamma,
                 const float* __restrict__ beta) {
    extern __shared__ float sm[];
    float* sW = sm;             // 128 cols x 32 float4-chunks (swizzled) = 64KB
    float* sX = sm + 16384;     // 64 rows x 128 = 32KB
    const float* X = (Xext != nullptr) ? Xext : g_bufB;
    int tid = threadIdx.x;
    int scol = tid & 127;       // staging column (also BN column)
    int srow = tid >> 7;        // staging row offset (0/1)

    float myScale = 1.f, myShift = 0.f;
    if (bnLayer >= 0) {
        float invN = 1.0f / (float)N_NODES;
        float mean = g_bnsum[bnLayer * FDIM + scol] * invN;
        float var = g_bnsq[bnLayer * FDIM + scol] * invN - mean * mean;
        myScale = rsqrtf(var + BN_EPS) * gamma[scol];
        myShift = beta[scol] - mean * myScale;
    }

    // stage W transposed + swizzled: sW[c*128 + (kq^(c&7))*4 + kr] = W[k*128+c]
    for (int i = tid; i < 128 * 128; i += 256) {
        int k = i >> 7, cw = i & 127;
        int kq = k >> 2, kr = k & 3;
        sW[cw * 128 + (((kq ^ (cw & 7)) << 2) | kr)] = W[i];
    }
    int row0 = blockIdx.x * 64;
    int nr = N_NODES - row0; if (nr > 64) nr = 64;   // 64 or 32
    for (int j = srow; j < nr; j += 2) {
        float v = X[(size_t)(row0 + j) * 128 + scol];
        if (bnLayer >= 0) v = fmaxf(v * myScale + myShift, 0.f);
        sX[j * 128 + scol] = v;
    }
    __syncthreads();

    int c = tid & 63;                 // owns cols c and c+64
    int rbase = (tid >> 6) * 16;      // 16 rows per thread (warp-uniform)

    ull acc[32];
#pragma unroll
    for (int i = 0; i < 32; i++) acc[i] = 0ull;

#pragma unroll 2
    for (int kq = 0; kq < 32; kq++) {
        int sw = kq ^ (c & 7);        // (c+64)&7 == c&7
        ulonglong2 wa = *reinterpret_cast<const ulonglong2*>(&sW[c * 128 + sw * 4]);
        ulonglong2 wb = *reinterpret_cast<const ulonglong2*>(&sW[(c + 64) * 128 + sw * 4]);
#pragma unroll
        for (int i = 0; i < 16; i++) {
            ulonglong2 xq = *reinterpret_cast<const ulonglong2*>(&sX[(rbase + i) * 128 + kq * 4]);
            asm("fma.rn.f32x2 %0,%1,%2,%0;" : "+l"(acc[2 * i])     : "l"(xq.x), "l"(wa.x));
            asm("fma.rn.f32x2 %0,%1,%2,%0;" : "+l"(acc[2 * i])     : "l"(xq.y), "l"(wa.y));
            asm("fma.rn.f32x2 %0,%1,%2,%0;" : "+l"(acc[2 * i + 1]) : "l"(xq.x), "l"(wb.x));
            asm("fma.rn.f32x2 %0,%1,%2,%0;" : "+l"(acc[2 * i + 1]) : "l"(xq.y), "l"(wb.y));
        }
    }

    if (rbase < nr) {                 // nr is a multiple of 16
#pragma unroll
        for (int i = 0; i < 16; i++) {
            int row = row0 + rbase + i;
            float lo, hi;
            asm("mov.b64 {%0,%1},%2;" : "=f"(lo), "=f"(hi) : "l"(acc[2 * i]));
            g_bufA[(size_t)row * 128 + c] = lo + hi;
            asm("mov.b64 {%0,%1},%2;" : "=f"(lo), "=f"(hi) : "l"(acc[2 * i + 1]));
            g_bufA[(size_t)row * 128 + c + 64] = lo + hi;
        }
    }
}

// ------------------------------- SpMM gather ---------------------------------
// bufB[n] = sum_{e: dst=n} h[src]*dis[src]*dis[n] + h[n]*dis[n]^2 + b
// One warp per node; lane l owns cols [4l,4l+4). Inner loop unrolled x4 to keep
// 4 gathers in flight (breaks the shfl->load->fma serial chain). BN stats fused.
__global__ void spmm_kernel(const float* __restrict__ bias, int layer) {
    __shared__ float sred[8 * 128];
    int gtid = blockIdx.x * blockDim.x + threadIdx.x;
    int warp = gtid >> 5;
    int wloc = threadIdx.x >> 5;
    int lane = threadIdx.x & 31;
    int nwarps = (gridDim.x * blockDim.x) >> 5;
    float4 bv = reinterpret_cast<const float4*>(bias)[lane];

    float4 ps = make_float4(0.f, 0.f, 0.f, 0.f);
    float4 pq = make_float4(0.f, 0.f, 0.f, 0.f);

    for (int n = warp; n < N_NODES; n += nwarps) {
        float dn = g_dis[n];
        float sl = dn * dn;
        float4 hs = *reinterpret_cast<const float4*>(&g_bufA[(size_t)n * 128 + lane * 4]);
        float4 acc;
        acc.x = hs.x * sl + bv.x;
        acc.y = hs.y * sl + bv.y;
        acc.z = hs.z * sl + bv.z;
        acc.w = hs.w * sl + bv.w;

        int s0 = g_rowptr[n], s1 = g_rowptr[n + 1];
        for (int base = s0; base < s1; base += 32) {
            int j = base + lane;
            int sj = 0; float wj = 0.f;
            if (j < s1) {
                int2 e = g_csrp[j];
                sj = e.x;
                wj = __int_as_float(e.y) * dn;
            }
            int cnt = s1 - base; if (cnt > 32) cnt = 32;
            int t = 0;
#pragma unroll 1
            for (; t + 4 <= cnt; t += 4) {
                int a0 = __shfl_sync(0xffffffffu, sj, t);
                int a1 = __shfl_sync(0xffffffffu, sj, t + 1);
                int a2 = __shfl_sync(0xffffffffu, sj, t + 2);
                int a3 = __shfl_sync(0xffffffffu, sj, t + 3);
                float w0 = __shfl_sync(0xffffffffu, wj, t);
                float w1 = __shfl_sync(0xffffffffu, wj, t + 1);
                float w2 = __shfl_sync(0xffffffffu, wj, t + 2);
                float w3 = __shfl_sync(0xffffffffu, wj, t + 3);
                float4 h0 = *reinterpret_cast<const float4*>(&g_bufA[(size_t)a0 * 128 + lane * 4]);
                float4 h1 = *reinterpret_cast<const float4*>(&g_bufA[(size_t)a1 * 128 + lane * 4]);
                float4 h2 = *reinterpret_cast<const float4*>(&g_bufA[(size_t)a2 * 128 + lane * 4]);
                float4 h3 = *reinterpret_cast<const float4*>(&g_bufA[(size_t)a3 * 128 + lane * 4]);
                acc.x += h0.x * w0; acc.y += h0.y * w0; acc.z += h0.z * w0; acc.w += h0.w * w0;
                acc.x += h1.x * w1; acc.y += h1.y * w1; acc.z += h1.z * w1; acc.w += h1.w * w1;
                acc.x += h2.x * w2; acc.y += h2.y * w2; acc.z += h2.z * w2; acc.w += h2.w * w2;
                acc.x += h3.x * w3; acc.y += h3.y * w3; acc.z += h3.z * w3; acc.w += h3.w * w3;
            }
#pragma unroll 1
            for (; t < cnt; t++) {
                int s = __shfl_sync(0xffffffffu, sj, t);
                float w = __shfl_sync(0xffffffffu, wj, t);
                float4 hv = *reinterpret_cast<const float4*>(&g_bufA[(size_t)s * 128 + lane * 4]);
                acc.x += hv.x * w;
                acc.y += hv.y * w;
                acc.z += hv.z * w;
                acc.w += hv.w * w;
            }
        }
        *reinterpret_cast<float4*>(&g_bufB[(size_t)n * 128 + lane * 4]) = acc;

        ps.x += acc.x; ps.y += acc.y; ps.z += acc.z; ps.w += acc.w;
        pq.x += acc.x * acc.x; pq.y += acc.y * acc.y;
        pq.z += acc.z * acc.z; pq.w += acc.w * acc.w;
    }

    float4* s4 = reinterpret_cast<float4*>(sred);
    s4[wloc * 32 + lane] = ps;
    __syncthreads();
    if (threadIdx.x < 128) {
        float tsum = 0.f;
        for (int ww = 0; ww < 8; ww++) tsum += sred[ww * 128 + threadIdx.x];
        atomicAdd(&g_bnsum[layer * FDIM + threadIdx.x], tsum);
    }
    __syncthreads();
    s4[wloc * 32 + lane] = pq;
    __syncthreads();
    if (threadIdx.x < 128) {
        float tsq = 0.f;
        for (int ww = 0; ww < 8; ww++) tsq += sred[ww * 128 + threadIdx.x];
        atomicAdd(&g_bnsq[layer * FDIM + threadIdx.x], tsq);
    }
}

// ---------------------------------- Pool -------------------------------------
__global__ void pool_kernel(const int* __restrict__ batch,
                            const float* __restrict__ gamma,
                            const float* __restrict__ beta) {
    int c = threadIdx.x;
    float invN = 1.0f / (float)N_NODES;
    float mean = g_bnsum[2 * FDIM + c] * invN;
    float var = g_bnsq[2 * FDIM + c] * invN - mean * mean;
    float scale = rsqrtf(var + BN_EPS) * gamma[c];
    float shift = beta[c] - mean * scale;

    int start = blockIdx.x * POOL_CHUNK;
    int end = start + POOL_CHUNK; if (end > N_NODES) end = N_NODES;
    if (start >= end) return;
    float acc = 0.f;
    int cur = batch[start];
    int cnt = 0;
    for (int r = start; r < end; r++) {
        int g = batch[r];
        if (g != cur) {
            atomicAdd(&g_pool[cur * FDIM + c], acc);
            if (c == 0) atomicAdd(&g_cnt[cur], (float)cnt);
            acc = 0.f; cnt = 0; cur = g;
        }
        float v = g_bufB[(size_t)r * 128 + c];
        acc += fmaxf(v * scale + shift, 0.f);
        cnt++;
    }
    atomicAdd(&g_pool[cur * FDIM + c], acc);
    if (c == 0) atomicAdd(&g_cnt[cur], (float)cnt);
}

// -------------------------------- Classifier ---------------------------------
__global__ void classify_kernel(const float* __restrict__ lw1, const float* __restrict__ lb1,
                                const float* __restrict__ lw2, const float* __restrict__ lb2,
                                float* __restrict__ out) {
    __shared__ float p[FDIM], h[FDIM], lo[N_CLASSES];
    int g = blockIdx.x;
    int c = threadIdx.x;
    float cv = fmaxf(g_cnt[g], 1.0f);
    p[c] = g_pool[g * FDIM + c] / cv;
    __syncthreads();
    float a = lb1[c];
    for (int k = 0; k < FDIM; k++) a += p[k] * lw1[k * FDIM + c];
    h[c] = fmaxf(a, 0.f);
    __syncthreads();
    if (c < N_CLASSES) {
        float a2 = lb2[c];
        for (int k = 0; k < FDIM; k++) a2 += h[k] * lw2[k * N_CLASSES + c];
        lo[c] = a2;
    }
    __syncthreads();
    if (c == 0) {
        float m = lo[0];
        for (int j = 1; j < N_CLASSES; j++) m = fmaxf(m, lo[j]);
        float s = 0.f;
        for (int j = 0; j < N_CLASSES; j++) s += expf(lo[j] - m);
        float L = m + logf(s);
        for (int j = 0; j < N_CLASSES; j++) out[g * N_CLASSES + j] = lo[j] - L;
    }
}

// --------------------------------- launch ------------------------------------
extern "C" void kernel_launch(void* const* d_in, const int* in_sizes, int n_in,
                              void* d_out, int out_size) {
    const float* x = (const float*)d_in[0];
    const int* ei = (const int*)d_in[1];
    const int* src = ei;
    const int* dst = ei + N_EDGES;
    const int* batch = (const int*)d_in[2];
    const float* W[3]     = { (const float*)d_in[3], (const float*)d_in[7],  (const float*)d_in[11] };
    const float* b[3]     = { (const float*)d_in[4], (const float*)d_in[8],  (const float*)d_in[12] };
    const float* gamma[3] = { (const float*)d_in[5], (const float*)d_in[9],  (const float*)d_in[13] };
    const float* beta[3]  = { (const float*)d_in[6], (const float*)d_in[10], (const float*)d_in[14] };
    const float* lin1_w = (const float*)d_in[15];
    const float* lin1_b = (const float*)d_in[16];
    const float* lin2_w = (const float*)d_in[17];
    const float* lin2_b = (const float*)d_in[18];
    float* out = (float*)d_out;

    cudaFuncSetAttribute(gemm_kernel, cudaFuncAttributeMaxDynamicSharedMemorySize, 98304);

    int gemm_blocks = (N_NODES + 63) / 64;

    // Launch order keeps gemm0 at index 3 and spmm0 at index 5 (ncu -s 5 -c 1).
    zero_kernel<<<224, 256>>>();                                     // 0
    hist_kernel<<<(N_EDGES + 255) / 256, 256>>>(dst);                // 1
    scan_fused_kernel<<<1, SCAN_THREADS>>>();                        // 2
    gemm_kernel<<<gemm_blocks, 256, 98304>>>(x, W[0], -1, nullptr, nullptr);  // 3
    fill_kernel<<<(N_EDGES + 255) / 256, 256>>>(src, dst);           // 4
    spmm_kernel<<<1184, 256>>>(b[0], 0);                             // 5
    gemm_kernel<<<gemm_blocks, 256, 98304>>>(nullptr, W[1], 0, gamma[0], beta[0]); // 6
    spmm_kernel<<<1184, 256>>>(b[1], 1);                             // 7
    gemm_kernel<<<gemm_blocks, 256, 98304>>>(nullptr, W[2], 1, gamma[1], beta[1]); // 8
    spmm_kernel<<<1184, 256>>>(b[2], 2);                             // 9
    pool_kernel<<<NB_POOL, 128>>>(batch, gamma[2], beta[2]);         // 10
    classify_kernel<<<N_GRAPHS, 128>>>(lin1_w, lin1_b, lin2_w, lin2_b, out); // 11
}

// round 12
// speedup vs baseline: 1.8131x; 1.0735x over previous
#include <cuda_runtime.h>
#include <cuda_fp16.h>
#include <math.h>

#define N_NODES 100000
#define N_EDGES 1600000
#define FDIM 128
#define N_GRAPHS 100
#define N_CLASSES 10
#define BN_EPS 1e-5f
#define SCAN_THREADS 1024
#define NB_SCAN ((N_NODES + SCAN_THREADS - 1) / SCAN_THREADS)   // 98
#define POOL_CHUNK 256
#define NB_POOL ((N_NODES + POOL_CHUNK - 1) / POOL_CHUNK)

typedef unsigned long long ull;

// Column storage permutation: logical col l -> storage col (l<64 ? 2l : 2(l-64)+1).
// invp maps storage -> logical.
__device__ __forceinline__ int invp(int s) { return (s & 1) ? 64 + (s >> 1) : (s >> 1); }

// ------------------------- scratch (static device globals) -------------------
__device__ __half g_bufH[(size_t)N_NODES * FDIM]; // h = x @ W (fp16, storage layout)
__device__ float  g_bufB[(size_t)N_NODES * FDIM]; // agg pre-BN (fp32, storage layout)
__device__ float  g_dis[N_NODES];                 // deg^{-1/2}
__device__ int    g_hist[N_NODES];
__device__ int    g_rowptr[N_NODES + 1];
__device__ int    g_cursor[N_NODES];
__device__ int2   g_csrp[N_EDGES];                // {src, bitcast(dis[src])}
__device__ float  g_bnsum[3 * FDIM];              // stats per STORAGE col
__device__ float  g_bnsq[3 * FDIM];
__device__ float  g_pool[N_GRAPHS * FDIM];        // storage layout
__device__ float  g_cnt[N_GRAPHS];

// ------------------------------ init / zero ----------------------------------
__global__ void zero_kernel() {
    int i = blockIdx.x * blockDim.x + threadIdx.x;
    int stride = gridDim.x * blockDim.x;
    for (int j = i; j < N_NODES; j += stride) g_hist[j] = 0;
    for (int j = i; j < N_GRAPHS * FDIM; j += stride) g_pool[j] = 0.f;
    for (int j = i; j < N_GRAPHS; j += stride) g_cnt[j] = 0.f;
    for (int j = i; j < 3 * FDIM; j += stride) { g_bnsum[j] = 0.f; g_bnsq[j] = 0.f; }
}

__global__ void hist_kernel(const int* __restrict__ dst) {
    int e = blockIdx.x * blockDim.x + threadIdx.x;
    if (e < N_EDGES) atomicAdd(&g_hist[dst[e]], 1);
}

// ------------------ fused scan (rowptr + cursor + dis), 1 block --------------
__global__ void scan_fused_kernel() {
    __shared__ int swt[32];
    __shared__ int s_carry;
    int t = threadIdx.x;
    int lane = t & 31;
    int w = t >> 5;
    if (t == 0) s_carry = 0;
    __syncthreads();

    for (int chunk = 0; chunk < NB_SCAN; chunk++) {
        int idx = chunk * SCAN_THREADS + t;
        int v = (idx < N_NODES) ? g_hist[idx] : 0;
        int s = v;
#pragma unroll
        for (int o = 1; o < 32; o <<= 1) {
            int n = __shfl_up_sync(0xffffffffu, s, o);
            if (lane >= o) s += n;
        }
        if (lane == 31) swt[w] = s;
        __syncthreads();
        if (w == 0) {
            int ws = swt[lane];
#pragma unroll
            for (int o = 1; o < 32; o <<= 1) {
                int n = __shfl_up_sync(0xffffffffu, ws, o);
                if (lane >= o) ws += n;
            }
            swt[lane] = ws;
        }
        __syncthreads();
        int incl = s + ((w > 0) ? swt[w - 1] : 0);
        int base = s_carry;
        int excl = base + incl - v;
        if (idx < N_NODES) {
            g_rowptr[idx] = excl;
            g_cursor[idx] = excl;
            g_dis[idx] = rsqrtf((float)v + 1.0f);
        }
        __syncthreads();
        if (t == SCAN_THREADS - 1) s_carry = base + incl;
        __syncthreads();
    }
    if (t == 0) g_rowptr[N_NODES] = s_carry;
}

__global__ void fill_kernel(const int* __restrict__ src, const int* __restrict__ dst) {
    int e = blockIdx.x * blockDim.x + threadIdx.x;
    if (e < N_EDGES) {
        int s = src[e], d = dst[e];
        int pos = atomicAdd(&g_cursor[d], 1);
        g_csrp[pos] = make_int2(s, __float_as_int(g_dis[s]));
    }
}

// --------------------------------- GEMM --------------------------------------
// g_bufH(storage) = fp16( relu(BN(X)) @ W ).  X storage layout for layers 1,2
// (bufB); external x (logical layout) permuted on load for layer 0.
// W staged transposed+swizzled with rows permuted by invp so that sX's storage
// k-order matches. Thread owns storage cols (2c, 2c+1) == logical (c, c+64),
// written as one coalesced __half2 per row.
__global__ __launch_bounds__(256, 2)
void gemm_kernel(const float* __restrict__ Xext, const float* __restrict__ W,
                 int bnLayer, const float* __restrict__ gamma,
                 const float* __restrict__ beta) {
    extern __shared__ float sm[];
    float* sW = sm;             // 128 cols x 128 (swizzled, rows = storage k)
    float* sX = sm + 16384;     // 64 rows x 128 (storage cols)
    int tid = threadIdx.x;
    int scol = tid & 127;       // staging storage column
    int srow = tid >> 7;

    float myScale = 1.f, myShift = 0.f;
    if (bnLayer >= 0) {
        float invN = 1.0f / (float)N_NODES;
        float mean = g_bnsum[bnLayer * FDIM + scol] * invN;
        float var = g_bnsq[bnLayer * FDIM + scol] * invN - mean * mean;
        int lc = invp(scol);
        myScale = rsqrtf(var + BN_EPS) * gamma[lc];
        myShift = beta[lc] - mean * myScale;
    }

    // stage W transposed + swizzled, storage-k rows: sW[c*128 + (kq^(c&7))*4+kr]
    //   = W[invp(k)][c]
    for (int i = tid; i < 128 * 128; i += 256) {
        int k = i >> 7, cw = i & 127;
        int kq = k >> 2, kr = k & 3;
        sW[cw * 128 + (((kq ^ (cw & 7)) << 2) | kr)] = W[invp(k) * 128 + cw];
    }
    int row0 = blockIdx.x * 64;
    int nr = N_NODES - row0; if (nr > 64) nr = 64;   // 64 or 32
    if (bnLayer >= 0) {
        for (int j = srow; j < nr; j += 2) {
            float v = g_bufB[(size_t)(row0 + j) * 128 + scol];
            sX[j * 128 + scol] = fmaxf(v * myScale + myShift, 0.f);
        }
    } else {
        int lc = invp(scol);
        for (int j = srow; j < nr; j += 2)
            sX[j * 128 + scol] = Xext[(size_t)(row0 + j) * 128 + lc];
    }
    __syncthreads();

    int c = tid & 63;                 // storage cols 2c, 2c+1
    int rbase = (tid >> 6) * 16;      // 16 rows per thread (warp-uniform)

    ull acc[32];
#pragma unroll
    for (int i = 0; i < 32; i++) acc[i] = 0ull;

#pragma unroll 2
    for (int kq = 0; kq < 32; kq++) {
        int sw = kq ^ (c & 7);        // (c+64)&7 == c&7
        ulonglong2 wa = *reinterpret_cast<const ulonglong2*>(&sW[c * 128 + sw * 4]);
        ulonglong2 wb = *reinterpret_cast<const ulonglong2*>(&sW[(c + 64) * 128 + sw * 4]);
#pragma unroll
        for (int i = 0; i < 16; i++) {
            ulonglong2 xq = *reinterpret_cast<const ulonglong2*>(&sX[(rbase + i) * 128 + kq * 4]);
            asm("fma.rn.f32x2 %0,%1,%2,%0;" : "+l"(acc[2 * i])     : "l"(xq.x), "l"(wa.x));
            asm("fma.rn.f32x2 %0,%1,%2,%0;" : "+l"(acc[2 * i])     : "l"(xq.y), "l"(wa.y));
            asm("fma.rn.f32x2 %0,%1,%2,%0;" : "+l"(acc[2 * i + 1]) : "l"(xq.x), "l"(wb.x));
            asm("fma.rn.f32x2 %0,%1,%2,%0;" : "+l"(acc[2 * i + 1]) : "l"(xq.y), "l"(wb.y));
        }
    }

    if (rbase < nr) {
#pragma unroll
        for (int i = 0; i < 16; i++) {
            int row = row0 + rbase + i;
            float lo, hi, v0, v1;
            asm("mov.b64 {%0,%1},%2;" : "=f"(lo), "=f"(hi) : "l"(acc[2 * i]));
            v0 = lo + hi;                       // logical col c   -> storage 2c
            asm("mov.b64 {%0,%1},%2;" : "=f"(lo), "=f"(hi) : "l"(acc[2 * i + 1]));
            v1 = lo + hi;                       // logical col c+64 -> storage 2c+1
            __half2 hv = __float22half2_rn(make_float2(v0, v1));
            *reinterpret_cast<__half2*>(&g_bufH[(size_t)row * 128 + 2 * c]) = hv;
        }
    }
}

// ------------------------------- SpMM gather ---------------------------------
// bufB[n] = sum_{e: dst=n} h[src]*dis[src]*dis[n] + h[n]*dis[n]^2 + b
// h gathered as fp16 (256B/row -> halves L2 traffic). One warp per node; lane l
// owns storage cols [4l,4l+4). fp32 accumulate; BN stats fused (storage cols).
__global__ void spmm_kernel(const float* __restrict__ bias, int layer) {
    __shared__ float sred[8 * 128];
    int gtid = blockIdx.x * blockDim.x + threadIdx.x;
    int warp = gtid >> 5;
    int wloc = threadIdx.x >> 5;
    int lane = threadIdx.x & 31;
    int nwarps = (gridDim.x * blockDim.x) >> 5;
    float4 bv;
    bv.x = bias[invp(4 * lane)];
    bv.y = bias[invp(4 * lane + 1)];
    bv.z = bias[invp(4 * lane + 2)];
    bv.w = bias[invp(4 * lane + 3)];

    float4 ps = make_float4(0.f, 0.f, 0.f, 0.f);
    float4 pq = make_float4(0.f, 0.f, 0.f, 0.f);

    for (int n = warp; n < N_NODES; n += nwarps) {
        float dn = g_dis[n];
        float sl = dn * dn;
        uint2 rs = *reinterpret_cast<const uint2*>(&g_bufH[(size_t)n * 128 + lane * 4]);
        float2 f0 = __half22float2(*reinterpret_cast<__half2*>(&rs.x));
        float2 f1 = __half22float2(*reinterpret_cast<__half2*>(&rs.y));
        float4 acc;
        acc.x = f0.x * sl + bv.x;
        acc.y = f0.y * sl + bv.y;
        acc.z = f1.x * sl + bv.z;
        acc.w = f1.y * sl + bv.w;

        int s0 = g_rowptr[n], s1 = g_rowptr[n + 1];
        for (int base = s0; base < s1; base += 32) {
            int j = base + lane;
            int sj = 0; float wj = 0.f;
            if (j < s1) {
                int2 e = g_csrp[j];
                sj = e.x;
                wj = __int_as_float(e.y) * dn;
            }
            int cnt = s1 - base; if (cnt > 32) cnt = 32;
            int t = 0;
#pragma unroll 1
            for (; t + 4 <= cnt; t += 4) {
                int a0 = __shfl_sync(0xffffffffu, sj, t);
                int a1 = __shfl_sync(0xffffffffu, sj, t + 1);
                int a2 = __shfl_sync(0xffffffffu, sj, t + 2);
                int a3 = __shfl_sync(0xffffffffu, sj, t + 3);
                float w0 = __shfl_sync(0xffffffffu, wj, t);
                float w1 = __shfl_sync(0xffffffffu, wj, t + 1);
                float w2 = __shfl_sync(0xffffffffu, wj, t + 2);
                float w3 = __shfl_sync(0xffffffffu, wj, t + 3);
                uint2 r0 = *reinterpret_cast<const uint2*>(&g_bufH[(size_t)a0 * 128 + lane * 4]);
                uint2 r1 = *reinterpret_cast<const uint2*>(&g_bufH[(size_t)a1 * 128 + lane * 4]);
                uint2 r2 = *reinterpret_cast<const uint2*>(&g_bufH[(size_t)a2 * 128 + lane * 4]);
                uint2 r3 = *reinterpret_cast<const uint2*>(&g_bufH[(size_t)a3 * 128 + lane * 4]);
                float2 a_, b_;
                a_ = __half22float2(*reinterpret_cast<__half2*>(&r0.x));
                b_ = __half22float2(*reinterpret_cast<__half2*>(&r0.y));
                acc.x += a_.x * w0; acc.y += a_.y * w0; acc.z += b_.x * w0; acc.w += b_.y * w0;
                a_ = __half22float2(*reinterpret_cast<__half2*>(&r1.x));
                b_ = __half22float2(*reinterpret_cast<__half2*>(&r1.y));
                acc.x += a_.x * w1; acc.y += a_.y * w1; acc.z += b_.x * w1; acc.w += b_.y * w1;
                a_ = __half22float2(*reinterpret_cast<__half2*>(&r2.x));
                b_ = __half22float2(*reinterpret_cast<__half2*>(&r2.y));
                acc.x += a_.x * w2; acc.y += a_.y * w2; acc.z += b_.x * w2; acc.w += b_.y * w2;
                a_ = __half22float2(*reinterpret_cast<__half2*>(&r3.x));
                b_ = __half22float2(*reinterpret_cast<__half2*>(&r3.y));
                acc.x += a_.x * w3; acc.y += a_.y * w3; acc.z += b_.x * w3; acc.w += b_.y * w3;
            }
#pragma unroll 1
            for (; t < cnt; t++) {
                int s = __shfl_sync(0xffffffffu, sj, t);
                float w = __shfl_sync(0xffffffffu, wj, t);
                uint2 rv = *reinterpret_cast<const uint2*>(&g_bufH[(size_t)s * 128 + lane * 4]);
                float2 a_ = __half22float2(*reinterpret_cast<__half2*>(&rv.x));
                float2 b_ = __half22float2(*reinterpret_cast<__half2*>(&rv.y));
                acc.x += a_.x * w; acc.y += a_.y * w;
                acc.z += b_.x * w; acc.w += b_.y * w;
            }
        }
        *reinterpret_cast<float4*>(&g_bufB[(size_t)n * 128 + lane * 4]) = acc;

        ps.x += acc.x; ps.y += acc.y; ps.z += acc.z; ps.w += acc.w;
        pq.x += acc.x * acc.x; pq.y += acc.y * acc.y;
        pq.z += acc.z * acc.z; pq.w += acc.w * acc.w;
    }

    float4* s4 = reinterpret_cast<float4*>(sred);
    s4[wloc * 32 + lane] = ps;
    __syncthreads();
    if (threadIdx.x < 128) {
        float tsum = 0.f;
        for (int ww = 0; ww < 8; ww++) tsum += sred[ww * 128 + threadIdx.x];
        atomicAdd(&g_bnsum[layer * FDIM + threadIdx.x], tsum);
    }
    __syncthreads();
    s4[wloc * 32 + lane] = pq;
    __syncthreads();
    if (threadIdx.x < 128) {
        float tsq = 0.f;
        for (int ww = 0; ww < 8; ww++) tsq += sred[ww * 128 + threadIdx.x];
        atomicAdd(&g_bnsq[layer * FDIM + threadIdx.x], tsq);
    }
}

// ---------------------------------- Pool -------------------------------------
// Applies layer-2 BN + ReLU on the fly (storage cols). batch is sorted.
__global__ void pool_kernel(const int* __restrict__ batch,
                            const float* __restrict__ gamma,
                            const float* __restrict__ beta) {
    int c = threadIdx.x;                     // storage col
    int lc = invp(c);
    float invN = 1.0f / (float)N_NODES;
    float mean = g_bnsum[2 * FDIM + c] * invN;
    float var = g_bnsq[2 * FDIM + c] * invN - mean * mean;
    float scale = rsqrtf(var + BN_EPS) * gamma[lc];
    float shift = beta[lc] - mean * scale;

    int start = blockIdx.x * POOL_CHUNK;
    int end = start + POOL_CHUNK; if (end > N_NODES) end = N_NODES;
    if (start >= end) return;
    float acc = 0.f;
    int cur = batch[start];
    int cnt = 0;
    for (int r = start; r < end; r++) {
        int g = batch[r];
        if (g != cur) {
            atomicAdd(&g_pool[cur * FDIM + c], acc);
            if (c == 0) atomicAdd(&g_cnt[cur], (float)cnt);
            acc = 0.f; cnt = 0; cur = g;
        }
        float v = g_bufB[(size_t)r * 128 + c];
        acc += fmaxf(v * scale + shift, 0.f);
        cnt++;
    }
    atomicAdd(&g_pool[cur * FDIM + c], acc);
    if (c == 0) atomicAdd(&g_cnt[cur], (float)cnt);
}

// -------------------------------- Classifier ---------------------------------
// p[] is in storage layout; lin1 rows indexed via invp.
__global__ void classify_kernel(const float* __restrict__ lw1, const float* __restrict__ lb1,
                                const float* __restrict__ lw2, const float* __restrict__ lb2,
                                float* __restrict__ out) {
    __shared__ float p[FDIM], h[FDIM], lo[N_CLASSES];
    int g = blockIdx.x;
    int c = threadIdx.x;
    float cv = fmaxf(g_cnt[g], 1.0f);
    p[c] = g_pool[g * FDIM + c] / cv;
    __syncthreads();
    float a = lb1[c];
    for (int s = 0; s < FDIM; s++) a += p[s] * lw1[invp(s) * FDIM + c];
    h[c] = fmaxf(a, 0.f);
    __syncthreads();
    if (c < N_CLASSES) {
        float a2 = lb2[c];
        for (int k = 0; k < FDIM; k++) a2 += h[k] * lw2[k * N_CLASSES + c];
        lo[c] = a2;
    }
    __syncthreads();
    if (c == 0) {
        float m = lo[0];
        for (int j = 1; j < N_CLASSES; j++) m = fmaxf(m, lo[j]);
        float s = 0.f;
        for (int j = 0; j < N_CLASSES; j++) s += expf(lo[j] - m);
        float L = m + logf(s);
        for (int j = 0; j < N_CLASSES; j++) out[g * N_CLASSES + j] = lo[j] - L;
    }
}

// --------------------------------- launch ------------------------------------
extern "C" void kernel_launch(void* const* d_in, const int* in_sizes, int n_in,
                              void* d_out, int out_size) {
    const float* x = (const float*)d_in[0];
    const int* ei = (const int*)d_in[1];
    const int* src = ei;
    const int* dst = ei + N_EDGES;
    const int* batch = (const int*)d_in[2];
    const float* W[3]     = { (const float*)d_in[3], (const float*)d_in[7],  (const float*)d_in[11] };
    const float* b[3]     = { (const float*)d_in[4], (const float*)d_in[8],  (const float*)d_in[12] };
    const float* gamma[3] = { (const float*)d_in[5], (const float*)d_in[9],  (const float*)d_in[13] };
    const float* beta[3]  = { (const float*)d_in[6], (const float*)d_in[10], (const float*)d_in[14] };
    const float* lin1_w = (const float*)d_in[15];
    const float* lin1_b = (const float*)d_in[16];
    const float* lin2_w = (const float*)d_in[17];
    const float* lin2_b = (const float*)d_in[18];
    float* out = (float*)d_out;

    cudaFuncSetAttribute(gemm_kernel, cudaFuncAttributeMaxDynamicSharedMemorySize, 98304);

    int gemm_blocks = (N_NODES + 63) / 64;

    // Launch order keeps gemm0 at index 3 and spmm0 at index 5 (ncu -s 5 -c 1).
    zero_kernel<<<224, 256>>>();                                     // 0
    hist_kernel<<<(N_EDGES + 255) / 256, 256>>>(dst);                // 1
    scan_fused_kernel<<<1, SCAN_THREADS>>>();                        // 2
    gemm_kernel<<<gemm_blocks, 256, 98304>>>(x, W[0], -1, nullptr, nullptr);  // 3
    fill_kernel<<<(N_EDGES + 255) / 256, 256>>>(src, dst);           // 4
    spmm_kernel<<<1184, 256>>>(b[0], 0);                             // 5
    gemm_kernel<<<gemm_blocks, 256, 98304>>>(nullptr, W[1], 0, gamma[0], beta[0]); // 6
    spmm_kernel<<<1184, 256>>>(b[1], 1);                             // 7
    gemm_kernel<<<gemm_blocks, 256, 98304>>>(nullptr, W[2], 1, gamma[1], beta[1]); // 8
    spmm_kernel<<<1184, 256>>>(b[2], 2);                             // 9
    pool_kernel<<<NB_POOL, 128>>>(batch, gamma[2], beta[2]);         // 10
    classify_kernel<<<N_GRAPHS, 128>>>(lin1_w, lin1_b, lin2_w, lin2_b, out); // 11
}

// round 13
// speedup vs baseline: 2.2377x; 1.2341x over previous
#include <cuda_runtime.h>
#include <cuda_fp16.h>
#include <math.h>

#define N_NODES 100000
#define N_EDGES 1600000
#define FDIM 128
#define N_GRAPHS 100
#define N_CLASSES 10
#define BN_EPS 1e-5f
#define SCAN_THREADS 1024
#define NB_SCAN ((N_NODES + SCAN_THREADS - 1) / SCAN_THREADS)   // 98
#define POOL_CHUNK 256
#define NB_POOL ((N_NODES + POOL_CHUNK - 1) / POOL_CHUNK)
#define XPAD 136                         // fp16 row stride in smem (conflict-free LDSM)

typedef unsigned long long ull;

// ------------------------- scratch (static device globals) -------------------
__device__ __half g_bufH[(size_t)N_NODES * FDIM]; // h = x @ W (fp16)
__device__ float  g_bufB[(size_t)N_NODES * FDIM]; // agg pre-BN (fp32)
__device__ float  g_dis[N_NODES];                 // deg^{-1/2}
__device__ int    g_hist[N_NODES];
__device__ int    g_rowptr[N_NODES + 1];
__device__ int    g_cursor[N_NODES];
__device__ int2   g_csrp[N_EDGES];                // {src, bitcast(dis[src])}
__device__ float  g_bnsum[3 * FDIM];
__device__ float  g_bnsq[3 * FDIM];
__device__ float  g_pool[N_GRAPHS * FDIM];
__device__ float  g_cnt[N_GRAPHS];

// ------------------------------ init / zero ----------------------------------
__global__ void zero_kernel() {
    int i = blockIdx.x * blockDim.x + threadIdx.x;
    int stride = gridDim.x * blockDim.x;
    for (int j = i; j < N_NODES; j += stride) g_hist[j] = 0;
    for (int j = i; j < N_GRAPHS * FDIM; j += stride) g_pool[j] = 0.f;
    for (int j = i; j < N_GRAPHS; j += stride) g_cnt[j] = 0.f;
    for (int j = i; j < 3 * FDIM; j += stride) { g_bnsum[j] = 0.f; g_bnsq[j] = 0.f; }
}

__global__ void hist_kernel(const int* __restrict__ dst) {
    int e = blockIdx.x * blockDim.x + threadIdx.x;
    if (e < N_EDGES) atomicAdd(&g_hist[dst[e]], 1);
}

// ------------------ fused scan (rowptr + cursor + dis), 1 block --------------
__global__ void scan_fused_kernel() {
    __shared__ int swt[32];
    __shared__ int s_carry;
    int t = threadIdx.x;
    int lane = t & 31;
    int w = t >> 5;
    if (t == 0) s_carry = 0;
    __syncthreads();

    for (int chunk = 0; chunk < NB_SCAN; chunk++) {
        int idx = chunk * SCAN_THREADS + t;
        int v = (idx < N_NODES) ? g_hist[idx] : 0;
        int s = v;
#pragma unroll
        for (int o = 1; o < 32; o <<= 1) {
            int n = __shfl_up_sync(0xffffffffu, s, o);
            if (lane >= o) s += n;
        }
        if (lane == 31) swt[w] = s;
        __syncthreads();
        if (w == 0) {
            int ws = swt[lane];
#pragma unroll
            for (int o = 1; o < 32; o <<= 1) {
                int n = __shfl_up_sync(0xffffffffu, ws, o);
                if (lane >= o) ws += n;
            }
            swt[lane] = ws;
        }
        __syncthreads();
        int incl = s + ((w > 0) ? swt[w - 1] : 0);
        int base = s_carry;
        int excl = base + incl - v;
        if (idx < N_NODES) {
            g_rowptr[idx] = excl;
            g_cursor[idx] = excl;
            g_dis[idx] = rsqrtf((float)v + 1.0f);
        }
        __syncthreads();
        if (t == SCAN_THREADS - 1) s_carry = base + incl;
        __syncthreads();
    }
    if (t == 0) g_rowptr[N_NODES] = s_carry;
}

__global__ void fill_kernel(const int* __restrict__ src, const int* __restrict__ dst) {
    int e = blockIdx.x * blockDim.x + threadIdx.x;
    if (e < N_EDGES) {
        int s = src[e], d = dst[e];
        int pos = atomicAdd(&g_cursor[d], 1);
        g_csrp[pos] = make_int2(s, __float_as_int(g_dis[s]));
    }
}

// ----------------------------- HMMA GEMM -------------------------------------
// g_bufH = fp16( relu(BN(X)) @ W ).  mma.sync.m16n8k16.f32.f16.f16.f32.
// CTA: 256 thr / 8 warps, tile 128 rows x 128 cols, K=128 in 8 k16 steps.
// Warp (w&3) owns rows 32*(w&3); (w>>2) owns cols 64*(w>>2).
// X and W staged as fp16, stride XPAD=136 halves => LDSM conflict-free
// (row step = 272B = 4 banks; 8 rows hit 8 distinct bank-quads).
__global__ __launch_bounds__(256, 2)
void gemm_kernel(const float* __restrict__ Xext, const float* __restrict__ W,
                 int bnLayer, const float* __restrict__ gamma,
                 const float* __restrict__ beta) {
    extern __shared__ __half smh[];
    __half* sX = smh;                   // 128 x XPAD
    __half* sW = smh + 128 * XPAD;      // 128(k) x XPAD(n)
    int tid = threadIdx.x;
    int row0 = blockIdx.x * 128;
    int nr = N_NODES - row0; if (nr > 128) nr = 128;   // 128 or 32

    // ---- stage W (fp32 -> fp16), [k][n] row-major, float4 per thread ----
    int cg = (tid & 31) * 4;            // col group
    int rp = tid >> 5;                  // row phase (0..7)
    for (int k = rp; k < 128; k += 8) {
        float4 wv = *reinterpret_cast<const float4*>(&W[(size_t)k * 128 + cg]);
        __half2 h0 = __float22half2_rn(make_float2(wv.x, wv.y));
        __half2 h1 = __float22half2_rn(make_float2(wv.z, wv.w));
        *reinterpret_cast<__half2*>(&sW[k * XPAD + cg]) = h0;
        *reinterpret_cast<__half2*>(&sW[k * XPAD + cg + 2]) = h1;
    }

    // ---- stage X with fused BN+ReLU (layers 1,2) ----
    float4 sc4 = make_float4(1.f, 1.f, 1.f, 1.f);
    float4 sh4 = make_float4(0.f, 0.f, 0.f, 0.f);
    if (bnLayer >= 0) {
        float invN = 1.0f / (float)N_NODES;
        float4 su = *reinterpret_cast<const float4*>(&g_bnsum[bnLayer * FDIM + cg]);
        float4 sq = *reinterpret_cast<const float4*>(&g_bnsq[bnLayer * FDIM + cg]);
        float4 ga = *reinterpret_cast<const float4*>(&gamma[cg]);
        float4 be = *reinterpret_cast<const float4*>(&beta[cg]);
        float m, v;
        m = su.x * invN; v = sq.x * invN - m * m; sc4.x = rsqrtf(v + BN_EPS) * ga.x; sh4.x = be.x - m * sc4.x;
        m = su.y * invN; v = sq.y * invN - m * m; sc4.y = rsqrtf(v + BN_EPS) * ga.y; sh4.y = be.y - m * sc4.y;
        m = su.z * invN; v = sq.z * invN - m * m; sc4.z = rsqrtf(v + BN_EPS) * ga.z; sh4.z = be.z - m * sc4.z;
        m = su.w * invN; v = sq.w * invN - m * m; sc4.w = rsqrtf(v + BN_EPS) * ga.w; sh4.w = be.w - m * sc4.w;
    }
    const float* X = (bnLayer >= 0) ? g_bufB : Xext;
    for (int j = rp; j < 128; j += 8) {
        float4 xv = make_float4(0.f, 0.f, 0.f, 0.f);
        if (j < nr) {
            xv = *reinterpret_cast<const float4*>(&X[(size_t)(row0 + j) * 128 + cg]);
            if (bnLayer >= 0) {
                xv.x = fmaxf(xv.x * sc4.x + sh4.x, 0.f);
                xv.y = fmaxf(xv.y * sc4.y + sh4.y, 0.f);
                xv.z = fmaxf(xv.z * sc4.z + sh4.z, 0.f);
                xv.w = fmaxf(xv.w * sc4.w + sh4.w, 0.f);
            }
        }
        __half2 h0 = __float22half2_rn(make_float2(xv.x, xv.y));
        __half2 h1 = __float22half2_rn(make_float2(xv.z, xv.w));
        *reinterpret_cast<__half2*>(&sX[j * XPAD + cg]) = h0;
        *reinterpret_cast<__half2*>(&sX[j * XPAD + cg + 2]) = h1;
    }
    __syncthreads();

    // ---- mma mainloop ----
    int warp = tid >> 5, lane = tid & 31;
    int rbase = (warp & 3) * 32;
    int cbase = (warp >> 2) * 64;

    unsigned sx_u = (unsigned)__cvta_generic_to_shared(sX);
    unsigned sw_u = (unsigned)__cvta_generic_to_shared(sW);

    // A ldmatrix.x4 lane addr: rows rbase + (lane&7) + ((lane&8)?8:0), k + ((lane&16)?8:0)
    unsigned aBase = sx_u + (unsigned)(((rbase + (lane & 7) + ((lane & 8) ? 8 : 0)) * XPAD
                                        + ((lane & 16) ? 8 : 0)) * 2);
    // B ldmatrix.x4.trans lane addr: k rows (lane&7)+((lane&8)?8:0), cols cbase + ((lane&16)?8:0)
    unsigned bBase = sw_u + (unsigned)((((lane & 7) + ((lane & 8) ? 8 : 0)) * XPAD
                                        + cbase + ((lane & 16) ? 8 : 0)) * 2);

    float c[2][8][4];
#pragma unroll
    for (int mi = 0; mi < 2; mi++)
#pragma unroll
        for (int ni = 0; ni < 8; ni++)
#pragma unroll
            for (int q = 0; q < 4; q++) c[mi][ni][q] = 0.f;

#pragma unroll
    for (int ks = 0; ks < 8; ks++) {
        unsigned a[2][4];
#pragma unroll
        for (int mi = 0; mi < 2; mi++) {
            unsigned addr = aBase + (unsigned)(ks * 32 + mi * 16 * XPAD * 2);
            asm volatile("ldmatrix.sync.aligned.m8n8.x4.shared.b16 {%0,%1,%2,%3}, [%4];"
                         : "=r"(a[mi][0]), "=r"(a[mi][1]), "=r"(a[mi][2]), "=r"(a[mi][3])
                         : "r"(addr));
        }
        unsigned b[4][4];   // p -> n-tiles 2p, 2p+1
#pragma unroll
        for (int p = 0; p < 4; p++) {
            unsigned addr = bBase + (unsigned)(ks * 16 * XPAD * 2 + p * 32);
            asm volatile("ldmatrix.sync.aligned.m8n8.x4.trans.shared.b16 {%0,%1,%2,%3}, [%4];"
                         : "=r"(b[p][0]), "=r"(b[p][1]), "=r"(b[p][2]), "=r"(b[p][3])
                         : "r"(addr));
        }
#pragma unroll
        for (int mi = 0; mi < 2; mi++) {
#pragma unroll
            for (int p = 0; p < 4; p++) {
                asm volatile(
                    "mma.sync.aligned.m16n8k16.row.col.f32.f16.f16.f32 "
                    "{%0,%1,%2,%3}, {%4,%5,%6,%7}, {%8,%9}, {%0,%1,%2,%3};"
                    : "+f"(c[mi][2 * p][0]), "+f"(c[mi][2 * p][1]),
                      "+f"(c[mi][2 * p][2]), "+f"(c[mi][2 * p][3])
                    : "r"(a[mi][0]), "r"(a[mi][1]), "r"(a[mi][2]), "r"(a[mi][3]),
                      "r"(b[p][0]), "r"(b[p][1]));
                asm volatile(
                    "mma.sync.aligned.m16n8k16.row.col.f32.f16.f16.f32 "
                    "{%0,%1,%2,%3}, {%4,%5,%6,%7}, {%8,%9}, {%0,%1,%2,%3};"
                    : "+f"(c[mi][2 * p + 1][0]), "+f"(c[mi][2 * p + 1][1]),
                      "+f"(c[mi][2 * p + 1][2]), "+f"(c[mi][2 * p + 1][3])
                    : "r"(a[mi][0]), "r"(a[mi][1]), "r"(a[mi][2]), "r"(a[mi][3]),
                      "r"(b[p][2]), "r"(b[p][3]));
            }
        }
    }

    // ---- epilogue: fp16 stores (thread holds adjacent col pairs) ----
    int grp = lane >> 2, qid = lane & 3;
#pragma unroll
    for (int mi = 0; mi < 2; mi++) {
        int r1 = rbase + 16 * mi + grp;
        int r2 = r1 + 8;
#pragma unroll
        for (int ni = 0; ni < 8; ni++) {
            int col = cbase + 8 * ni + qid * 2;
            if (r1 < nr)
                *reinterpret_cast<__half2*>(&g_bufH[(size_t)(row0 + r1) * 128 + col]) =
                    __float22half2_rn(make_float2(c[mi][ni][0], c[mi][ni][1]));
            if (r2 < nr)
                *reinterpret_cast<__half2*>(&g_bufH[(size_t)(row0 + r2) * 128 + col]) =
                    __float22half2_rn(make_float2(c[mi][ni][2], c[mi][ni][3]));
        }
    }
}

// ------------------------------- SpMM gather ---------------------------------
// bufB[n] = sum_{e: dst=n} h[src]*dis[src]*dis[n] + h[n]*dis[n]^2 + b
// h gathered as fp16. One warp per node; lane l owns cols [4l,4l+4).
// fp32 accumulate; BN column stats fused.
__global__ void spmm_kernel(const float* __restrict__ bias, int layer) {
    __shared__ float sred[8 * 128];
    int gtid = blockIdx.x * blockDim.x + threadIdx.x;
    int warp = gtid >> 5;
    int wloc = threadIdx.x >> 5;
    int lane = threadIdx.x & 31;
    int nwarps = (gridDim.x * blockDim.x) >> 5;
    float4 bv = reinterpret_cast<const float4*>(bias)[lane];

    float4 ps = make_float4(0.f, 0.f, 0.f, 0.f);
    float4 pq = make_float4(0.f, 0.f, 0.f, 0.f);

    for (int n = warp; n < N_NODES; n += nwarps) {
        float dn = g_dis[n];
        float sl = dn * dn;
        uint2 rs = *reinterpret_cast<const uint2*>(&g_bufH[(size_t)n * 128 + lane * 4]);
        float2 f0 = __half22float2(*reinterpret_cast<__half2*>(&rs.x));
        float2 f1 = __half22float2(*reinterpret_cast<__half2*>(&rs.y));
        float4 acc;
        acc.x = f0.x * sl + bv.x;
        acc.y = f0.y * sl + bv.y;
        acc.z = f1.x * sl + bv.z;
        acc.w = f1.y * sl + bv.w;

        int s0 = g_rowptr[n], s1 = g_rowptr[n + 1];
        for (int base = s0; base < s1; base += 32) {
            int j = base + lane;
            int sj = 0; float wj = 0.f;
            if (j < s1) {
                int2 e = g_csrp[j];
                sj = e.x;
                wj = __int_as_float(e.y) * dn;
            }
            int cnt = s1 - base; if (cnt > 32) cnt = 32;
            int t = 0;
#pragma unroll 1
            for (; t + 4 <= cnt; t += 4) {
                int a0 = __shfl_sync(0xffffffffu, sj, t);
                int a1 = __shfl_sync(0xffffffffu, sj, t + 1);
                int a2 = __shfl_sync(0xffffffffu, sj, t + 2);
                int a3 = __shfl_sync(0xffffffffu, sj, t + 3);
                float w0 = __shfl_sync(0xffffffffu, wj, t);
                float w1 = __shfl_sync(0xffffffffu, wj, t + 1);
                float w2 = __shfl_sync(0xffffffffu, wj, t + 2);
                float w3 = __shfl_sync(0xffffffffu, wj, t + 3);
                uint2 r0 = *reinterpret_cast<const uint2*>(&g_bufH[(size_t)a0 * 128 + lane * 4]);
                uint2 r1 = *reinterpret_cast<const uint2*>(&g_bufH[(size_t)a1 * 128 + lane * 4]);
                uint2 r2 = *reinterpret_cast<const uint2*>(&g_bufH[(size_t)a2 * 128 + lane * 4]);
                uint2 r3 = *reinterpret_cast<const uint2*>(&g_bufH[(size_t)a3 * 128 + lane * 4]);
                float2 a_, b_;
                a_ = __half22float2(*reinterpret_cast<__half2*>(&r0.x));
                b_ = __half22float2(*reinterpret_cast<__half2*>(&r0.y));
                acc.x += a_.x * w0; acc.y += a_.y * w0; acc.z += b_.x * w0; acc.w += b_.y * w0;
                a_ = __half22float2(*reinterpret_cast<__half2*>(&r1.x));
                b_ = __half22float2(*reinterpret_cast<__half2*>(&r1.y));
                acc.x += a_.x * w1; acc.y += a_.y * w1; acc.z += b_.x * w1; acc.w += b_.y * w1;
                a_ = __half22float2(*reinterpret_cast<__half2*>(&r2.x));
                b_ = __half22float2(*reinterpret_cast<__half2*>(&r2.y));
                acc.x += a_.x * w2; acc.y += a_.y * w2; acc.z += b_.x * w2; acc.w += b_.y * w2;
                a_ = __half22float2(*reinterpret_cast<__half2*>(&r3.x));
                b_ = __half22float2(*reinterpret_cast<__half2*>(&r3.y));
                acc.x += a_.x * w3; acc.y += a_.y * w3; acc.z += b_.x * w3; acc.w += b_.y * w3;
            }
#pragma unroll 1
            for (; t < cnt; t++) {
                int s = __shfl_sync(0xffffffffu, sj, t);
                float w = __shfl_sync(0xffffffffu, wj, t);
                uint2 rv = *reinterpret_cast<const uint2*>(&g_bufH[(size_t)s * 128 + lane * 4]);
                float2 a_ = __half22float2(*reinterpret_cast<__half2*>(&rv.x));
                float2 b_ = __half22float2(*reinterpret_cast<__half2*>(&rv.y));
                acc.x += a_.x * w; acc.y += a_.y * w;
                acc.z += b_.x * w; acc.w += b_.y * w;
            }
        }
        *reinterpret_cast<float4*>(&g_bufB[(size_t)n * 128 + lane * 4]) = acc;

        ps.x += acc.x; ps.y += acc.y; ps.z += acc.z; ps.w += acc.w;
        pq.x += acc.x * acc.x; pq.y += acc.y * acc.y;
        pq.z += acc.z * acc.z; pq.w += acc.w * acc.w;
    }

    float4* s4 = reinterpret_cast<float4*>(sred);
    s4[wloc * 32 + lane] = ps;
    __syncthreads();
    if (threadIdx.x < 128) {
        float tsum = 0.f;
        for (int ww = 0; ww < 8; ww++) tsum += sred[ww * 128 + threadIdx.x];
        atomicAdd(&g_bnsum[layer * FDIM + threadIdx.x], tsum);
    }
    __syncthreads();
    s4[wloc * 32 + lane] = pq;
    __syncthreads();
    if (threadIdx.x < 128) {
        float tsq = 0.f;
        for (int ww = 0; ww < 8; ww++) tsq += sred[ww * 128 + threadIdx.x];
        atomicAdd(&g_bnsq[layer * FDIM + threadIdx.x], tsq);
    }
}

// ---------------------------------- Pool -------------------------------------
// Applies layer-2 BN + ReLU on the fly. batch is sorted.
__global__ void pool_kernel(const int* __restrict__ batch,
                            const float* __restrict__ gamma,
                            const float* __restrict__ beta) {
    int c = threadIdx.x;
    float invN = 1.0f / (float)N_NODES;
    float mean = g_bnsum[2 * FDIM + c] * invN;
    float var = g_bnsq[2 * FDIM + c] * invN - mean * mean;
    float scale = rsqrtf(var + BN_EPS) * gamma[c];
    float shift = beta[c] - mean * scale;

    int start = blockIdx.x * POOL_CHUNK;
    int end = start + POOL_CHUNK; if (end > N_NODES) end = N_NODES;
    if (start >= end) return;
    float acc = 0.f;
    int cur = batch[start];
    int cnt = 0;
    for (int r = start; r < end; r++) {
        int g = batch[r];
        if (g != cur) {
            atomicAdd(&g_pool[cur * FDIM + c], acc);
            if (c == 0) atomicAdd(&g_cnt[cur], (float)cnt);
            acc = 0.f; cnt = 0; cur = g;
        }
        float v = g_bufB[(size_t)r * 128 + c];
        acc += fmaxf(v * scale + shift, 0.f);
        cnt++;
    }
    atomicAdd(&g_pool[cur * FDIM + c], acc);
    if (c == 0) atomicAdd(&g_cnt[cur], (float)cnt);
}

// -------------------------------- Classifier ---------------------------------
__global__ void classify_kernel(const float* __restrict__ lw1, const float* __restrict__ lb1,
                                const float* __restrict__ lw2, const float* __restrict__ lb2,
                                float* __restrict__ out) {
    __shared__ float p[FDIM], h[FDIM], lo[N_CLASSES];
    int g = blockIdx.x;
    int c = threadIdx.x;
    float cv = fmaxf(g_cnt[g], 1.0f);
    p[c] = g_pool[g * FDIM + c] / cv;
    __syncthreads();
    float a = lb1[c];
    for (int k = 0; k < FDIM; k++) a += p[k] * lw1[k * FDIM + c];
    h[c] = fmaxf(a, 0.f);
    __syncthreads();
    if (c < N_CLASSES) {
        float a2 = lb2[c];
        for (int k = 0; k < FDIM; k++) a2 += h[k] * lw2[k * N_CLASSES + c];
        lo[c] = a2;
    }
    __syncthreads();
    if (c == 0) {
        float m = lo[0];
        for (int j = 1; j < N_CLASSES; j++) m = fmaxf(m, lo[j]);
        float s = 0.f;
        for (int j = 0; j < N_CLASSES; j++) s += expf(lo[j] - m);
        float L = m + logf(s);
        for (int j = 0; j < N_CLASSES; j++) out[g * N_CLASSES + j] = lo[j] - L;
    }
}

// --------------------------------- launch ------------------------------------
extern "C" void kernel_launch(void* const* d_in, const int* in_sizes, int n_in,
                              void* d_out, int out_size) {
    const float* x = (const float*)d_in[0];
    const int* ei = (const int*)d_in[1];
    const int* src = ei;
    const int* dst = ei + N_EDGES;
    const int* batch = (const int*)d_in[2];
    const float* W[3]     = { (const float*)d_in[3], (const float*)d_in[7],  (const float*)d_in[11] };
    const float* b[3]     = { (const float*)d_in[4], (const float*)d_in[8],  (const float*)d_in[12] };
    const float* gamma[3] = { (const float*)d_in[5], (const float*)d_in[9],  (const float*)d_in[13] };
    const float* beta[3]  = { (const float*)d_in[6], (const float*)d_in[10], (const float*)d_in[14] };
    const float* lin1_w = (const float*)d_in[15];
    const float* lin1_b = (const float*)d_in[16];
    const float* lin2_w = (const float*)d_in[17];
    const float* lin2_b = (const float*)d_in[18];
    float* out = (float*)d_out;

    const int smem_gemm = 2 * 128 * XPAD * sizeof(__half);   // 69632 B
    cudaFuncSetAttribute(gemm_kernel, cudaFuncAttributeMaxDynamicSharedMemorySize, smem_gemm);

    int gemm_blocks = (N_NODES + 127) / 128;   // 782

    // Launch order keeps gemm0 at index 3 and spmm0 at index 5 (ncu -s 5 -c 1).
    zero_kernel<<<224, 256>>>();                                     // 0
    hist_kernel<<<(N_EDGES + 255) / 256, 256>>>(dst);                // 1
    scan_fused_kernel<<<1, SCAN_THREADS>>>();                        // 2
    gemm_kernel<<<gemm_blocks, 256, smem_gemm>>>(x, W[0], -1, nullptr, nullptr);  // 3
    fill_kernel<<<(N_EDGES + 255) / 256, 256>>>(src, dst);           // 4
    spmm_kernel<<<1184, 256>>>(b[0], 0);                             // 5
    gemm_kernel<<<gemm_blocks, 256, smem_gemm>>>(nullptr, W[1], 0, gamma[0], beta[0]); // 6
    spmm_kernel<<<1184, 256>>>(b[1], 1);                             // 7
    gemm_kernel<<<gemm_blocks, 256, smem_gemm>>>(nullptr, W[2], 1, gamma[1], beta[1]); // 8
    spmm_kernel<<<1184, 256>>>(b[2], 2);                             // 9
    pool_kernel<<<NB_POOL, 128>>>(batch, gamma[2], beta[2]);         // 10
    classify_kernel<<<N_GRAPHS, 128>>>(lin1_w, lin1_b, lin2_w, lin2_b, out); // 11
}

// round 16
// speedup vs baseline: 2.4577x; 1.0983x over previous
#include <cuda_runtime.h>
#include <cuda_fp16.h>
#include <math.h>

#define N_NODES 100000
#define N_EDGES 1600000
#define FDIM 128
#define N_GRAPHS 100
#define N_CLASSES 10
#define BN_EPS 1e-5f
#define SCAN_THREADS 1024
#define NB_SCAN ((N_NODES + SCAN_THREADS - 1) / SCAN_THREADS)   // 98
#define POOL_CHUNK 256
#define NB_POOL ((N_NODES + POOL_CHUNK - 1) / POOL_CHUNK)
#define XPAD 136                         // fp16 row stride in smem (conflict-free LDSM)

typedef unsigned long long ull;

// ------------------------- scratch (static device globals) -------------------
__device__ __align__(16) __half g_bufH[(size_t)N_NODES * FDIM];  // h = x @ W (fp16)
__device__ __align__(16) __half g_bufBh[(size_t)N_NODES * FDIM]; // agg pre-BN (fp16)
__device__ float  g_dis[N_NODES];                  // deg^{-1/2}
__device__ int    g_hist[N_NODES];
__device__ int    g_rowptr[N_NODES + 1];
__device__ int    g_cursor[N_NODES];
__device__ __align__(16) int2 g_csrp[N_EDGES];     // {src, bitcast(dis[src])}
__device__ float  g_bnsum[3 * FDIM];
__device__ float  g_bnsq[3 * FDIM];
__device__ float  g_pool[N_GRAPHS * FDIM];
__device__ float  g_cnt[N_GRAPHS];

__device__ __forceinline__ void h8_to_f8(uint4 r, float* f) {
    float2 t;
    t = __half22float2(*reinterpret_cast<__half2*>(&r.x)); f[0] = t.x; f[1] = t.y;
    t = __half22float2(*reinterpret_cast<__half2*>(&r.y)); f[2] = t.x; f[3] = t.y;
    t = __half22float2(*reinterpret_cast<__half2*>(&r.z)); f[4] = t.x; f[5] = t.y;
    t = __half22float2(*reinterpret_cast<__half2*>(&r.w)); f[6] = t.x; f[7] = t.y;
}

// ------------------------------ init / zero ----------------------------------
__global__ void zero_kernel() {
    int i = blockIdx.x * blockDim.x + threadIdx.x;
    int stride = gridDim.x * blockDim.x;
    for (int j = i; j < N_NODES; j += stride) g_hist[j] = 0;
    for (int j = i; j < N_GRAPHS * FDIM; j += stride) g_pool[j] = 0.f;
    for (int j = i; j < N_GRAPHS; j += stride) g_cnt[j] = 0.f;
    for (int j = i; j < 3 * FDIM; j += stride) { g_bnsum[j] = 0.f; g_bnsq[j] = 0.f; }
}

__global__ void hist_kernel(const int* __restrict__ dst) {
    int e = blockIdx.x * blockDim.x + threadIdx.x;
    if (e < N_EDGES) atomicAdd(&g_hist[dst[e]], 1);
}

// ------------------ fused scan (rowptr + cursor + dis), 1 block --------------
__global__ void scan_fused_kernel() {
    __shared__ int swt[32];
    __shared__ int s_carry;
    int t = threadIdx.x;
    int lane = t & 31;
    int w = t >> 5;
    if (t == 0) s_carry = 0;
    __syncthreads();

    for (int chunk = 0; chunk < NB_SCAN; chunk++) {
        int idx = chunk * SCAN_THREADS + t;
        int v = (idx < N_NODES) ? g_hist[idx] : 0;
        int s = v;
#pragma unroll
        for (int o = 1; o < 32; o <<= 1) {
            int n = __shfl_up_sync(0xffffffffu, s, o);
            if (lane >= o) s += n;
        }
        if (lane == 31) swt[w] = s;
        __syncthreads();
        if (w == 0) {
            int ws = swt[lane];
#pragma unroll
            for (int o = 1; o < 32; o <<= 1) {
                int n = __shfl_up_sync(0xffffffffu, ws, o);
                if (lane >= o) ws += n;
            }
            swt[lane] = ws;
        }
        __syncthreads();
        int incl = s + ((w > 0) ? swt[w - 1] : 0);
        int base = s_carry;
        int excl = base + incl - v;
        if (idx < N_NODES) {
            g_rowptr[idx] = excl;
            g_cursor[idx] = excl;
            g_dis[idx] = rsqrtf((float)v + 1.0f);
        }
        __syncthreads();
        if (t == SCAN_THREADS - 1) s_carry = base + incl;
        __syncthreads();
    }
    if (t == 0) g_rowptr[N_NODES] = s_carry;
}

__global__ void fill_kernel(const int* __restrict__ src, const int* __restrict__ dst) {
    int e = blockIdx.x * blockDim.x + threadIdx.x;
    if (e < N_EDGES) {
        int s = src[e], d = dst[e];
        int pos = atomicAdd(&g_cursor[d], 1);
        g_csrp[pos] = make_int2(s, __float_as_int(g_dis[s]));
    }
}

// ----------------------------- HMMA GEMM -------------------------------------
// g_bufH = fp16( relu(BN(X)) @ W ).  mma.sync.m16n8k16.f32.f16.f16.f32.
// CTA: 256 thr / 8 warps, tile 128x128, K=128 in 8 k16 steps.
__global__ __launch_bounds__(256, 2)
void gemm_kernel(const float* __restrict__ Xext, const float* __restrict__ W,
                 int bnLayer, const float* __restrict__ gamma,
                 const float* __restrict__ beta) {
    extern __shared__ __half smh[];
    __half* sX = smh;                   // 128 x XPAD
    __half* sW = smh + 128 * XPAD;      // 128(k) x XPAD(n)
    int tid = threadIdx.x;
    int row0 = blockIdx.x * 128;
    int nr = N_NODES - row0; if (nr > 128) nr = 128;   // 128 or 32

    // ---- stage W (fp32 -> fp16) ----
    int cg = (tid & 31) * 4;            // col group
    int rp = tid >> 5;                  // row phase (0..7)
    for (int k = rp; k < 128; k += 8) {
        float4 wv = *reinterpret_cast<const float4*>(&W[(size_t)k * 128 + cg]);
        *reinterpret_cast<__half2*>(&sW[k * XPAD + cg]) = __float22half2_rn(make_float2(wv.x, wv.y));
        *reinterpret_cast<__half2*>(&sW[k * XPAD + cg + 2]) = __float22half2_rn(make_float2(wv.z, wv.w));
    }

    // ---- stage X with fused BN+ReLU (layers 1,2) ----
    float4 sc4 = make_float4(1.f, 1.f, 1.f, 1.f);
    float4 sh4 = make_float4(0.f, 0.f, 0.f, 0.f);
    if (bnLayer >= 0) {
        float invN = 1.0f / (float)N_NODES;
        float4 su = *reinterpret_cast<const float4*>(&g_bnsum[bnLayer * FDIM + cg]);
        float4 sq = *reinterpret_cast<const float4*>(&g_bnsq[bnLayer * FDIM + cg]);
        float4 ga = *reinterpret_cast<const float4*>(&gamma[cg]);
        float4 be = *reinterpret_cast<const float4*>(&beta[cg]);
        float m, v;
        m = su.x * invN; v = sq.x * invN - m * m; sc4.x = rsqrtf(v + BN_EPS) * ga.x; sh4.x = be.x - m * sc4.x;
        m = su.y * invN; v = sq.y * invN - m * m; sc4.y = rsqrtf(v + BN_EPS) * ga.y; sh4.y = be.y - m * sc4.y;
        m = su.z * invN; v = sq.z * invN - m * m; sc4.z = rsqrtf(v + BN_EPS) * ga.z; sh4.z = be.z - m * sc4.z;
        m = su.w * invN; v = sq.w * invN - m * m; sc4.w = rsqrtf(v + BN_EPS) * ga.w; sh4.w = be.w - m * sc4.w;
    }
    for (int j = rp; j < 128; j += 8) {
        float4 xv = make_float4(0.f, 0.f, 0.f, 0.f);
        if (j < nr) {
            if (bnLayer >= 0) {
                uint2 hv = *reinterpret_cast<const uint2*>(&g_bufBh[(size_t)(row0 + j) * 128 + cg]);
                float2 a = __half22float2(*reinterpret_cast<__half2*>(&hv.x));
                float2 b = __half22float2(*reinterpret_cast<__half2*>(&hv.y));
                xv.x = fmaxf(a.x * sc4.x + sh4.x, 0.f);
                xv.y = fmaxf(a.y * sc4.y + sh4.y, 0.f);
                xv.z = fmaxf(b.x * sc4.z + sh4.z, 0.f);
                xv.w = fmaxf(b.y * sc4.w + sh4.w, 0.f);
            } else {
                xv = *reinterpret_cast<const float4*>(&Xext[(size_t)(row0 + j) * 128 + cg]);
            }
        }
        *reinterpret_cast<__half2*>(&sX[j * XPAD + cg]) = __float22half2_rn(make_float2(xv.x, xv.y));
        *reinterpret_cast<__half2*>(&sX[j * XPAD + cg + 2]) = __float22half2_rn(make_float2(xv.z, xv.w));
    }
    __syncthreads();

    // ---- mma mainloop ----
    int warp = tid >> 5, lane = tid & 31;
    int rbase = (warp & 3) * 32;
    int cbase = (warp >> 2) * 64;

    unsigned sx_u = (unsigned)__cvta_generic_to_shared(sX);
    unsigned sw_u = (unsigned)__cvta_generic_to_shared(sW);

    unsigned aBase = sx_u + (unsigned)(((rbase + (lane & 7) + ((lane & 8) ? 8 : 0)) * XPAD
                                        + ((lane & 16) ? 8 : 0)) * 2);
    unsigned bBase = sw_u + (unsigned)((((lane & 7) + ((lane & 8) ? 8 : 0)) * XPAD
                                        + cbase + ((lane & 16) ? 8 : 0)) * 2);

    float c[2][8][4];
#pragma unroll
    for (int mi = 0; mi < 2; mi++)
#pragma unroll
        for (int ni = 0; ni < 8; ni++)
#pragma unroll
            for (int q = 0; q < 4; q++) c[mi][ni][q] = 0.f;

#pragma unroll
    for (int ks = 0; ks < 8; ks++) {
        unsigned a[2][4];
#pragma unroll
        for (int mi = 0; mi < 2; mi++) {
            unsigned addr = aBase + (unsigned)(ks * 32 + mi * 16 * XPAD * 2);
            asm volatile("ldmatrix.sync.aligned.m8n8.x4.shared.b16 {%0,%1,%2,%3}, [%4];"
                         : "=r"(a[mi][0]), "=r"(a[mi][1]), "=r"(a[mi][2]), "=r"(a[mi][3])
                         : "r"(addr));
        }
        unsigned b[4][4];
#pragma unroll
        for (int p = 0; p < 4; p++) {
            unsigned addr = bBase + (unsigned)(ks * 16 * XPAD * 2 + p * 32);
            asm volatile("ldmatrix.sync.aligned.m8n8.x4.trans.shared.b16 {%0,%1,%2,%3}, [%4];"
                         : "=r"(b[p][0]), "=r"(b[p][1]), "=r"(b[p][2]), "=r"(b[p][3])
                         : "r"(addr));
        }
#pragma unroll
        for (int mi = 0; mi < 2; mi++) {
#pragma unroll
            for (int p = 0; p < 4; p++) {
                asm volatile(
                    "mma.sync.aligned.m16n8k16.row.col.f32.f16.f16.f32 "
                    "{%0,%1,%2,%3}, {%4,%5,%6,%7}, {%8,%9}, {%0,%1,%2,%3};"
                    : "+f"(c[mi][2 * p][0]), "+f"(c[mi][2 * p][1]),
                      "+f"(c[mi][2 * p][2]), "+f"(c[mi][2 * p][3])
                    : "r"(a[mi][0]), "r"(a[mi][1]), "r"(a[mi][2]), "r"(a[mi][3]),
                      "r"(b[p][0]), "r"(b[p][1]));
                asm volatile(
                    "mma.sync.aligned.m16n8k16.row.col.f32.f16.f16.f32 "
                    "{%0,%1,%2,%3}, {%4,%5,%6,%7}, {%8,%9}, {%0,%1,%2,%3};"
                    : "+f"(c[mi][2 * p + 1][0]), "+f"(c[mi][2 * p + 1][1]),
                      "+f"(c[mi][2 * p + 1][2]), "+f"(c[mi][2 * p + 1][3])
                    : "r"(a[mi][0]), "r"(a[mi][1]), "r"(a[mi][2]), "r"(a[mi][3]),
                      "r"(b[p][2]), "r"(b[p][3]));
            }
        }
    }

    // ---- epilogue: fp16 stores ----
    int grp = lane >> 2, qid = lane & 3;
#pragma unroll
    for (int mi = 0; mi < 2; mi++) {
        int r1 = rbase + 16 * mi + grp;
        int r2 = r1 + 8;
#pragma unroll
        for (int ni = 0; ni < 8; ni++) {
            int col = cbase + 8 * ni + qid * 2;
            if (r1 < nr)
                *reinterpret_cast<__half2*>(&g_bufH[(size_t)(row0 + r1) * 128 + col]) =
                    __float22half2_rn(make_float2(c[mi][ni][0], c[mi][ni][1]));
            if (r2 < nr)
                *reinterpret_cast<__half2*>(&g_bufH[(size_t)(row0 + r2) * 128 + col]) =
                    __float22half2_rn(make_float2(c[mi][ni][2], c[mi][ni][3]));
        }
    }
}

// ------------------------------- SpMM gather ---------------------------------
// bufBh[n] = fp16( sum_{e: dst=n} h[src]*dis[src]*dis[n] + h[n]*dis[n]^2 + b )
// TWO nodes per warp via 16-lane groups. ALL shfls inside the (divergent) node
// and edge loops use the GROUP-LOCAL mask — the two groups have different trip
// counts, so a full-warp mask there is UB (this was the R14/R15 crash).
__global__ void spmm_kernel(const float* __restrict__ bias, int layer) {
    __shared__ float sred[8 * 128];
    int gtid = blockIdx.x * blockDim.x + threadIdx.x;
    int warp = gtid >> 5;
    int wloc = threadIdx.x >> 5;
    int lane = threadIdx.x & 31;
    int grp = lane >> 4;                 // node sub-group 0/1
    int lg = lane & 15;                  // lane within group
    unsigned gmask = 0xFFFFu << (grp << 4);   // group-local shfl mask
    int nwarps = (gridDim.x * blockDim.x) >> 5;
    int node0 = warp * 2 + grp;
    int nstride = nwarps * 2;

    float bv[8];
#pragma unroll
    for (int q = 0; q < 8; q++) bv[q] = bias[lg * 8 + q];

    float ps[8], pq[8];
#pragma unroll
    for (int q = 0; q < 8; q++) { ps[q] = 0.f; pq[q] = 0.f; }

    for (int n = node0; n < N_NODES; n += nstride) {
        float dn = g_dis[n];
        float sl = dn * dn;
        uint4 rs = *reinterpret_cast<const uint4*>(&g_bufH[(size_t)n * 128 + lg * 8]);
        float f[8];
        h8_to_f8(rs, f);
        float acc[8];
#pragma unroll
        for (int q = 0; q < 8; q++) acc[q] = f[q] * sl + bv[q];

        int s0 = g_rowptr[n], s1 = g_rowptr[n + 1];
        for (int base = s0; base < s1; base += 16) {
            int j = base + lg;
            int sj = 0; float wj = 0.f;
            if (j < s1) {
                int2 e = g_csrp[j];
                sj = e.x;
                wj = __int_as_float(e.y) * dn;
            }
            int cnt = s1 - base; if (cnt > 16) cnt = 16;
            int t = 0;
#pragma unroll 1
            for (; t + 4 <= cnt; t += 4) {
                int a0 = __shfl_sync(gmask, sj, t, 16);
                int a1 = __shfl_sync(gmask, sj, t + 1, 16);
                int a2 = __shfl_sync(gmask, sj, t + 2, 16);
                int a3 = __shfl_sync(gmask, sj, t + 3, 16);
                float w0 = __shfl_sync(gmask, wj, t, 16);
                float w1 = __shfl_sync(gmask, wj, t + 1, 16);
                float w2 = __shfl_sync(gmask, wj, t + 2, 16);
                float w3 = __shfl_sync(gmask, wj, t + 3, 16);
                uint4 r0 = *reinterpret_cast<const uint4*>(&g_bufH[(size_t)a0 * 128 + lg * 8]);
                uint4 r1 = *reinterpret_cast<const uint4*>(&g_bufH[(size_t)a1 * 128 + lg * 8]);
                uint4 r2 = *reinterpret_cast<const uint4*>(&g_bufH[(size_t)a2 * 128 + lg * 8]);
                uint4 r3 = *reinterpret_cast<const uint4*>(&g_bufH[(size_t)a3 * 128 + lg * 8]);
                float g0[8], g1[8], g2[8], g3[8];
                h8_to_f8(r0, g0); h8_to_f8(r1, g1); h8_to_f8(r2, g2); h8_to_f8(r3, g3);
#pragma unroll
                for (int q = 0; q < 8; q++)
                    acc[q] += g0[q] * w0 + g1[q] * w1 + g2[q] * w2 + g3[q] * w3;
            }
#pragma unroll 1
            for (; t < cnt; t++) {
                int s = __shfl_sync(gmask, sj, t, 16);
                float w = __shfl_sync(gmask, wj, t, 16);
                uint4 rv = *reinterpret_cast<const uint4*>(&g_bufH[(size_t)s * 128 + lg * 8]);
                float g[8];
                h8_to_f8(rv, g);
#pragma unroll
                for (int q = 0; q < 8; q++) acc[q] += g[q] * w;
            }
        }
        // store fp16
        uint4 outv;
        *reinterpret_cast<__half2*>(&outv.x) = __float22half2_rn(make_float2(acc[0], acc[1]));
        *reinterpret_cast<__half2*>(&outv.y) = __float22half2_rn(make_float2(acc[2], acc[3]));
        *reinterpret_cast<__half2*>(&outv.z) = __float22half2_rn(make_float2(acc[4], acc[5]));
        *reinterpret_cast<__half2*>(&outv.w) = __float22half2_rn(make_float2(acc[6], acc[7]));
        *reinterpret_cast<uint4*>(&g_bufBh[(size_t)n * 128 + lg * 8]) = outv;

#pragma unroll
        for (int q = 0; q < 8; q++) { ps[q] += acc[q]; pq[q] += acc[q] * acc[q]; }
    }

    // combine the two groups (after reconvergence; lanes l, l^16 share cols)
#pragma unroll
    for (int q = 0; q < 8; q++) {
        ps[q] += __shfl_xor_sync(0xffffffffu, ps[q], 16);
        pq[q] += __shfl_xor_sync(0xffffffffu, pq[q], 16);
    }
    if (grp == 0) {
#pragma unroll
        for (int q = 0; q < 8; q++) sred[wloc * 128 + lg * 8 + q] = ps[q];
    }
    __syncthreads();
    if (threadIdx.x < 128) {
        float tsum = 0.f;
        for (int ww = 0; ww < 8; ww++) tsum += sred[ww * 128 + threadIdx.x];
        atomicAdd(&g_bnsum[layer * FDIM + threadIdx.x], tsum);
    }
    __syncthreads();
    if (grp == 0) {
#pragma unroll
        for (int q = 0; q < 8; q++) sred[wloc * 128 + lg * 8 + q] = pq[q];
    }
    __syncthreads();
    if (threadIdx.x < 128) {
        float tsq = 0.f;
        for (int ww = 0; ww < 8; ww++) tsq += sred[ww * 128 + threadIdx.x];
        atomicAdd(&g_bnsq[layer * FDIM + threadIdx.x], tsq);
    }
}

// ---------------------------------- Pool -------------------------------------
__global__ void pool_kernel(const int* __restrict__ batch,
                            const float* __restrict__ gamma,
                            const float* __restrict__ beta) {
    int c = threadIdx.x;
    float invN = 1.0f / (float)N_NODES;
    float mean = g_bnsum[2 * FDIM + c] * invN;
    float var = g_bnsq[2 * FDIM + c] * invN - mean * mean;
    float scale = rsqrtf(var + BN_EPS) * gamma[c];
    float shift = beta[c] - mean * scale;

    int start = blockIdx.x * POOL_CHUNK;
    int end = start + POOL_CHUNK; if (end > N_NODES) end = N_NODES;
    if (start >= end) return;
    float acc = 0.f;
    int cur = batch[start];
    int cnt = 0;
    for (int r = start; r < end; r++) {
        int g = batch[r];
        if (g != cur) {
            atomicAdd(&g_pool[cur * FDIM + c], acc);
            if (c == 0) atomicAdd(&g_cnt[cur], (float)cnt);
            acc = 0.f; cnt = 0; cur = g;
        }
        float v = __half2float(g_bufBh[(size_t)r * 128 + c]);
        acc += fmaxf(v * scale + shift, 0.f);
        cnt++;
    }
    atomicAdd(&g_pool[cur * FDIM + c], acc);
    if (c == 0) atomicAdd(&g_cnt[cur], (float)cnt);
}

// -------------------------------- Classifier ---------------------------------
__global__ void classify_kernel(const float* __restrict__ lw1, const float* __restrict__ lb1,
                                const float* __restrict__ lw2, const float* __restrict__ lb2,
                                float* __restrict__ out) {
    __shared__ float p[FDIM], h[FDIM], lo[N_CLASSES];
    int g = blockIdx.x;
    int c = threadIdx.x;
    float cv = fmaxf(g_cnt[g], 1.0f);
    p[c] = g_pool[g * FDIM + c] / cv;
    __syncthreads();
    float a = lb1[c];
    for (int k = 0; k < FDIM; k++) a += p[k] * lw1[k * FDIM + c];
    h[c] = fmaxf(a, 0.f);
    __syncthreads();
    if (c < N_CLASSES) {
        float a2 = lb2[c];
        for (int k = 0; k < FDIM; k++) a2 += h[k] * lw2[k * N_CLASSES + c];
        lo[c] = a2;
    }
    __syncthreads();
    if (c == 0) {
        float m = lo[0];
        for (int j = 1; j < N_CLASSES; j++) m = fmaxf(m, lo[j]);
        float s = 0.f;
        for (int j = 0; j < N_CLASSES; j++) s += expf(lo[j] - m);
        float L = m + logf(s);
        for (int j = 0; j < N_CLASSES; j++) out[g * N_CLASSES + j] = lo[j] - L;
    }
}

// --------------------------------- launch ------------------------------------
extern "C" void kernel_launch(void* const* d_in, const int* in_sizes, int n_in,
                              void* d_out, int out_size) {
    const float* x = (const float*)d_in[0];
    const int* ei = (const int*)d_in[1];
    const int* src = ei;
    const int* dst = ei + N_EDGES;
    const int* batch = (const int*)d_in[2];
    const float* W[3]     = { (const float*)d_in[3], (const float*)d_in[7],  (const float*)d_in[11] };
    const float* b[3]     = { (const float*)d_in[4], (const float*)d_in[8],  (const float*)d_in[12] };
    const float* gamma[3] = { (const float*)d_in[5], (const float*)d_in[9],  (const float*)d_in[13] };
    const float* beta[3]  = { (const float*)d_in[6], (const float*)d_in[10], (const float*)d_in[14] };
    const float* lin1_w = (const float*)d_in[15];
    const float* lin1_b = (const float*)d_in[16];
    const float* lin2_w = (const float*)d_in[17];
    const float* lin2_b = (const float*)d_in[18];
    float* out = (float*)d_out;

    const int smem_gemm = 2 * 128 * XPAD * sizeof(__half);   // 69632 B
    cudaFuncSetAttribute(gemm_kernel, cudaFuncAttributeMaxDynamicSharedMemorySize, smem_gemm);

    int gemm_blocks = (N_NODES + 127) / 128;   // 782

    zero_kernel<<<224, 256>>>();                                     // 0
    hist_kernel<<<(N_EDGES + 255) / 256, 256>>>(dst);                // 1
    scan_fused_kernel<<<1, SCAN_THREADS>>>();                        // 2
    gemm_kernel<<<gemm_blocks, 256, smem_gemm>>>(x, W[0], -1, nullptr, nullptr);  // 3
    fill_kernel<<<(N_EDGES + 255) / 256, 256>>>(src, dst);           // 4
    spmm_kernel<<<1184, 256>>>(b[0], 0);                             // 5
    gemm_kernel<<<gemm_blocks, 256, smem_gemm>>>(nullptr, W[1], 0, gamma[0], beta[0]); // 6
    spmm_kernel<<<1184, 256>>>(b[1], 1);                             // 7
    gemm_kernel<<<gemm_blocks, 256, smem_gemm>>>(nullptr, W[2], 1, gamma[1], beta[1]); // 8
    spmm_kernel<<<1184, 256>>>(b[2], 2);                             // 9
    pool_kernel<<<NB_POOL, 128>>>(batch, gamma[2], beta[2]);         // 10
    classify_kernel<<<N_GRAPHS, 128>>>(lin1_w, lin1_b, lin2_w, lin2_b, out); // 11
}

// round 17
// speedup vs baseline: 3.0360x; 1.2353x over previous
#include <cuda_runtime.h>
#include <cuda_fp16.h>
#include <math.h>

#define N_NODES 100000
#define N_EDGES 1600000
#define FDIM 128
#define N_GRAPHS 100
#define N_CLASSES 10
#define BN_EPS 1e-5f
#define SCAN_CHUNK 1024
#define NB_SCAN ((N_NODES + SCAN_CHUNK - 1) / SCAN_CHUNK)   // 98
#define POOL_CHUNK 256
#define NB_POOL ((N_NODES + POOL_CHUNK - 1) / POOL_CHUNK)
#define XPAD 136                         // fp16 row stride in smem (conflict-free LDSM)

typedef unsigned long long ull;

// ------------------------- scratch (static device globals) -------------------
__device__ __align__(16) __half g_bufH[(size_t)N_NODES * FDIM];  // h = x @ W (fp16)
__device__ __align__(16) __half g_bufBh[(size_t)N_NODES * FDIM]; // agg pre-BN (fp16)
__device__ __align__(16) __half g_Wh[3 * FDIM * FDIM];           // fp16 weights
__device__ float  g_dis[N_NODES];                  // deg^{-1/2}
__device__ int    g_hist[N_NODES];
__device__ int    g_rowptr[N_NODES + 1];
__device__ int    g_cursor[N_NODES];
__device__ __align__(16) int2 g_csrp[N_EDGES];     // {src, bitcast(dis[src])}
__device__ int    g_part[NB_SCAN + 1];
__device__ float  g_bnsum[3 * FDIM];
__device__ float  g_bnsq[3 * FDIM];
__device__ float  g_pool[N_GRAPHS * FDIM];
__device__ float  g_cnt[N_GRAPHS];

__device__ __forceinline__ void h8_to_f8(uint4 r, float* f) {
    float2 t;
    t = __half22float2(*reinterpret_cast<__half2*>(&r.x)); f[0] = t.x; f[1] = t.y;
    t = __half22float2(*reinterpret_cast<__half2*>(&r.y)); f[2] = t.x; f[3] = t.y;
    t = __half22float2(*reinterpret_cast<__half2*>(&r.z)); f[4] = t.x; f[5] = t.y;
    t = __half22float2(*reinterpret_cast<__half2*>(&r.w)); f[6] = t.x; f[7] = t.y;
}

__device__ __forceinline__ void cp_async16(unsigned saddr, const void* g) {
    asm volatile("cp.async.cg.shared.global [%0], [%1], 16;" :: "r"(saddr), "l"(g));
}

// ------------------------------ init / zero ----------------------------------
__global__ void zero_kernel() {
    int i = blockIdx.x * blockDim.x + threadIdx.x;
    int stride = gridDim.x * blockDim.x;
    for (int j = i; j < N_NODES; j += stride) g_hist[j] = 0;
    for (int j = i; j < N_GRAPHS * FDIM; j += stride) g_pool[j] = 0.f;
    for (int j = i; j < N_GRAPHS; j += stride) g_cnt[j] = 0.f;
    for (int j = i; j < 3 * FDIM; j += stride) { g_bnsum[j] = 0.f; g_bnsq[j] = 0.f; }
}

__global__ void hist_kernel(const int* __restrict__ dst) {
    int e = blockIdx.x * blockDim.x + threadIdx.x;
    if (e < N_EDGES) atomicAdd(&g_hist[dst[e]], 1);
}

// Convert all three W matrices to fp16 (once per launch).
__global__ void wconv_kernel(const float* __restrict__ W0, const float* __restrict__ W1,
                             const float* __restrict__ W2) {
    int i = blockIdx.x * blockDim.x + threadIdx.x;   // 0 .. 3*16384-1
    if (i < FDIM * FDIM)          g_Wh[i] = __float2half_rn(W0[i]);
    else if (i < 2 * FDIM * FDIM) g_Wh[i] = __float2half_rn(W1[i - FDIM * FDIM]);
    else if (i < 3 * FDIM * FDIM) g_Wh[i] = __float2half_rn(W2[i - 2 * FDIM * FDIM]);
}

// ------------------------- parallel scan (3 kernels) -------------------------
__global__ void scanA_kernel() {
    __shared__ int s[SCAN_CHUNK];
    int t = threadIdx.x;
    int idx = blockIdx.x * SCAN_CHUNK + t;
    s[t] = (idx < N_NODES) ? g_hist[idx] : 0;
    __syncthreads();
    for (int o = SCAN_CHUNK / 2; o > 0; o >>= 1) {
        if (t < o) s[t] += s[t + o];
        __syncthreads();
    }
    if (t == 0) g_part[blockIdx.x] = s[0];
}

__global__ void scanB_kernel() {
    int run = 0;
    for (int b = 0; b < NB_SCAN; b++) {
        int v = g_part[b];
        g_part[b] = run;
        run += v;
    }
}

__global__ void scanC_kernel() {
    __shared__ int s[SCAN_CHUNK];
    int t = threadIdx.x;
    int idx = blockIdx.x * SCAN_CHUNK + t;
    int v = (idx < N_NODES) ? g_hist[idx] : 0;
    s[t] = v;
    __syncthreads();
    for (int o = 1; o < SCAN_CHUNK; o <<= 1) {
        int a = (t >= o) ? s[t - o] : 0;
        __syncthreads();
        s[t] += a;
        __syncthreads();
    }
    if (idx < N_NODES) {
        int excl = g_part[blockIdx.x] + s[t] - v;
        g_rowptr[idx] = excl;
        g_cursor[idx] = excl;
        g_dis[idx] = rsqrtf((float)v + 1.0f);
        if (idx == N_NODES - 1) g_rowptr[N_NODES] = excl + v;
    }
}

__global__ void fill_kernel(const int* __restrict__ src, const int* __restrict__ dst) {
    int e = blockIdx.x * blockDim.x + threadIdx.x;
    if (e < N_EDGES) {
        int s = src[e], d = dst[e];
        int pos = atomicAdd(&g_cursor[d], 1);
        g_csrp[pos] = make_int2(s, __float_as_int(g_dis[s]));
    }
}

// ----------------------------- HMMA GEMM -------------------------------------
// g_bufH = fp16( relu(BN(X)) @ Wh[layer] ).  mma.sync.m16n8k16.
// W staged via cp.async (fp16 pre-converted); X staged with register-batched
// loads (MLP 8-16) + fused BN/ReLU for layers 1,2.
__global__ __launch_bounds__(256, 2)
void gemm_kernel(const float* __restrict__ Xext, int wLayer,
                 int bnLayer, const float* __restrict__ gamma,
                 const float* __restrict__ beta) {
    extern __shared__ __half smh[];
    __half* sX = smh;                   // 128 x XPAD
    __half* sW = smh + 128 * XPAD;      // 128(k) x XPAD(n)
    int tid = threadIdx.x;
    int row0 = blockIdx.x * 128;
    int nr = N_NODES - row0; if (nr > 128) nr = 128;   // 128 or 32

    // ---- stage W via cp.async (2048 x 16B chunks, 8 per thread) ----
    unsigned sw_u = (unsigned)__cvta_generic_to_shared(sW);
    const __half* Wh = g_Wh + (size_t)wLayer * FDIM * FDIM;
#pragma unroll
    for (int kk = 0; kk < 8; kk++) {
        int q = tid + 256 * kk;
        int row = q >> 4, c16 = q & 15;
        cp_async16(sw_u + (unsigned)(row * XPAD * 2 + c16 * 16), Wh + row * 128 + c16 * 8);
    }
    asm volatile("cp.async.commit_group;");

    // ---- stage X (register-batched) ----
    int cg = (tid & 31) * 4;            // col group
    int rp = tid >> 5;                  // row phase (0..7)
    if (bnLayer >= 0) {
        float4 sc4, sh4;
        float invN = 1.0f / (float)N_NODES;
        float4 su = *reinterpret_cast<const float4*>(&g_bnsum[bnLayer * FDIM + cg]);
        float4 sq = *reinterpret_cast<const float4*>(&g_bnsq[bnLayer * FDIM + cg]);
        float4 ga = *reinterpret_cast<const float4*>(&gamma[cg]);
        float4 be = *reinterpret_cast<const float4*>(&beta[cg]);
        float m, v;
        m = su.x * invN; v = sq.x * invN - m * m; sc4.x = rsqrtf(v + BN_EPS) * ga.x; sh4.x = be.x - m * sc4.x;
        m = su.y * invN; v = sq.y * invN - m * m; sc4.y = rsqrtf(v + BN_EPS) * ga.y; sh4.y = be.y - m * sc4.y;
        m = su.z * invN; v = sq.z * invN - m * m; sc4.z = rsqrtf(v + BN_EPS) * ga.z; sh4.z = be.z - m * sc4.z;
        m = su.w * invN; v = sq.w * invN - m * m; sc4.w = rsqrtf(v + BN_EPS) * ga.w; sh4.w = be.w - m * sc4.w;
        // 16 uint2 loads in flight, then convert+BN+store
        uint2 tmp[16];
#pragma unroll
        for (int t = 0; t < 16; t++) {
            int j = rp + 8 * t;
            tmp[t] = (j < nr) ? *reinterpret_cast<const uint2*>(&g_bufBh[(size_t)(row0 + j) * 128 + cg])
                              : make_uint2(0u, 0u);
        }
#pragma unroll
        for (int t = 0; t < 16; t++) {
            int j = rp + 8 * t;
            float2 a = __half22float2(*reinterpret_cast<__half2*>(&tmp[t].x));
            float2 b = __half22float2(*reinterpret_cast<__half2*>(&tmp[t].y));
            float x0 = fmaxf(a.x * sc4.x + sh4.x, 0.f);
            float x1 = fmaxf(a.y * sc4.y + sh4.y, 0.f);
            float x2 = fmaxf(b.x * sc4.z + sh4.z, 0.f);
            float x3 = fmaxf(b.y * sc4.w + sh4.w, 0.f);
            *reinterpret_cast<__half2*>(&sX[j * XPAD + cg]) = __float22half2_rn(make_float2(x0, x1));
            *reinterpret_cast<__half2*>(&sX[j * XPAD + cg + 2]) = __float22half2_rn(make_float2(x2, x3));
        }
    } else {
        // layer 0: fp32 input, two batches of 8 float4 in flight
#pragma unroll
        for (int hb = 0; hb < 2; hb++) {
            float4 tmp[8];
#pragma unroll
            for (int t = 0; t < 8; t++) {
                int j = rp + 8 * (hb * 8 + t);
                tmp[t] = (j < nr) ? *reinterpret_cast<const float4*>(&Xext[(size_t)(row0 + j) * 128 + cg])
                                  : make_float4(0.f, 0.f, 0.f, 0.f);
            }
#pragma unroll
            for (int t = 0; t < 8; t++) {
                int j = rp + 8 * (hb * 8 + t);
                *reinterpret_cast<__half2*>(&sX[j * XPAD + cg]) =
                    __float22half2_rn(make_float2(tmp[t].x, tmp[t].y));
                *reinterpret_cast<__half2*>(&sX[j * XPAD + cg + 2]) =
                    __float22half2_rn(make_float2(tmp[t].z, tmp[t].w));
            }
        }
    }
    asm volatile("cp.async.wait_group 0;");
    __syncthreads();

    // ---- mma mainloop ----
    int warp = tid >> 5, lane = tid & 31;
    int rbase = (warp & 3) * 32;
    int cbase = (warp >> 2) * 64;

    unsigned sx_u = (unsigned)__cvta_generic_to_shared(sX);

    unsigned aBase = sx_u + (unsigned)(((rbase + (lane & 7) + ((lane & 8) ? 8 : 0)) * XPAD
                                        + ((lane & 16) ? 8 : 0)) * 2);
    unsigned bBase = sw_u + (unsigned)((((lane & 7) + ((lane & 8) ? 8 : 0)) * XPAD
                                        + cbase + ((lane & 16) ? 8 : 0)) * 2);

    float c[2][8][4];
#pragma unroll
    for (int mi = 0; mi < 2; mi++)
#pragma unroll
        for (int ni = 0; ni < 8; ni++)
#pragma unroll
            for (int q = 0; q < 4; q++) c[mi][ni][q] = 0.f;

#pragma unroll
    for (int ks = 0; ks < 8; ks++) {
        unsigned a[2][4];
#pragma unroll
        for (int mi = 0; mi < 2; mi++) {
            unsigned addr = aBase + (unsigned)(ks * 32 + mi * 16 * XPAD * 2);
            asm volatile("ldmatrix.sync.aligned.m8n8.x4.shared.b16 {%0,%1,%2,%3}, [%4];"
                         : "=r"(a[mi][0]), "=r"(a[mi][1]), "=r"(a[mi][2]), "=r"(a[mi][3])
                         : "r"(addr));
        }
        unsigned b[4][4];
#pragma unroll
        for (int p = 0; p < 4; p++) {
            unsigned addr = bBase + (unsigned)(ks * 16 * XPAD * 2 + p * 32);
            asm volatile("ldmatrix.sync.aligned.m8n8.x4.trans.shared.b16 {%0,%1,%2,%3}, [%4];"
                         : "=r"(b[p][0]), "=r"(b[p][1]), "=r"(b[p][2]), "=r"(b[p][3])
                         : "r"(addr));
        }
#pragma unroll
        for (int mi = 0; mi < 2; mi++) {
#pragma unroll
            for (int p = 0; p < 4; p++) {
                asm volatile(
                    "mma.sync.aligned.m16n8k16.row.col.f32.f16.f16.f32 "
                    "{%0,%1,%2,%3}, {%4,%5,%6,%7}, {%8,%9}, {%0,%1,%2,%3};"
                    : "+f"(c[mi][2 * p][0]), "+f"(c[mi][2 * p][1]),
                      "+f"(c[mi][2 * p][2]), "+f"(c[mi][2 * p][3])
                    : "r"(a[mi][0]), "r"(a[mi][1]), "r"(a[mi][2]), "r"(a[mi][3]),
                      "r"(b[p][0]), "r"(b[p][1]));
                asm volatile(
                    "mma.sync.aligned.m16n8k16.row.col.f32.f16.f16.f32 "
                    "{%0,%1,%2,%3}, {%4,%5,%6,%7}, {%8,%9}, {%0,%1,%2,%3};"
                    : "+f"(c[mi][2 * p + 1][0]), "+f"(c[mi][2 * p + 1][1]),
                      "+f"(c[mi][2 * p + 1][2]), "+f"(c[mi][2 * p + 1][3])
                    : "r"(a[mi][0]), "r"(a[mi][1]), "r"(a[mi][2]), "r"(a[mi][3]),
                      "r"(b[p][2]), "r"(b[p][3]));
            }
        }
    }

    // ---- epilogue: fp16 stores ----
    int grp = lane >> 2, qid = lane & 3;
#pragma unroll
    for (int mi = 0; mi < 2; mi++) {
        int r1 = rbase + 16 * mi + grp;
        int r2 = r1 + 8;
#pragma unroll
        for (int ni = 0; ni < 8; ni++) {
            int col = cbase + 8 * ni + qid * 2;
            if (r1 < nr)
                *reinterpret_cast<__half2*>(&g_bufH[(size_t)(row0 + r1) * 128 + col]) =
                    __float22half2_rn(make_float2(c[mi][ni][0], c[mi][ni][1]));
            if (r2 < nr)
                *reinterpret_cast<__half2*>(&g_bufH[(size_t)(row0 + r2) * 128 + col]) =
                    __float22half2_rn(make_float2(c[mi][ni][2], c[mi][ni][3]));
        }
    }
}

// ------------------------------- SpMM gather ---------------------------------
// Two nodes per warp (16-lane groups, group-local shfl masks — divergent trip
// counts make full-warp masks UB). Pipeline depth 8: 16 gathers in flight/warp.
__global__ void spmm_kernel(const float* __restrict__ bias, int layer) {
    __shared__ float sred[8 * 128];
    int gtid = blockIdx.x * blockDim.x + threadIdx.x;
    int warp = gtid >> 5;
    int wloc = threadIdx.x >> 5;
    int lane = threadIdx.x & 31;
    int grp = lane >> 4;
    int lg = lane & 15;
    unsigned gmask = 0xFFFFu << (grp << 4);
    int nwarps = (gridDim.x * blockDim.x) >> 5;
    int node0 = warp * 2 + grp;
    int nstride = nwarps * 2;

    float bv[8];
#pragma unroll
    for (int q = 0; q < 8; q++) bv[q] = bias[lg * 8 + q];

    float ps[8], pq[8];
#pragma unroll
    for (int q = 0; q < 8; q++) { ps[q] = 0.f; pq[q] = 0.f; }

    for (int n = node0; n < N_NODES; n += nstride) {
        float dn = g_dis[n];
        float sl = dn * dn;
        uint4 rs = *reinterpret_cast<const uint4*>(&g_bufH[(size_t)n * 128 + lg * 8]);
        float f[8];
        h8_to_f8(rs, f);
        float acc[8];
#pragma unroll
        for (int q = 0; q < 8; q++) acc[q] = f[q] * sl + bv[q];

        int s0 = g_rowptr[n], s1 = g_rowptr[n + 1];
        for (int base = s0; base < s1; base += 16) {
            int j = base + lg;
            int sj = 0; float wj = 0.f;
            if (j < s1) {
                int2 e = g_csrp[j];
                sj = e.x;
                wj = __int_as_float(e.y) * dn;
            }
            int cnt = s1 - base; if (cnt > 16) cnt = 16;
            int t = 0;
#pragma unroll 1
            for (; t + 8 <= cnt; t += 8) {
                int av[8]; float wv[8];
#pragma unroll
                for (int u = 0; u < 8; u++) {
                    av[u] = __shfl_sync(gmask, sj, t + u, 16);
                    wv[u] = __shfl_sync(gmask, wj, t + u, 16);
                }
                uint4 rr[8];
#pragma unroll
                for (int u = 0; u < 8; u++)
                    rr[u] = *reinterpret_cast<const uint4*>(&g_bufH[(size_t)av[u] * 128 + lg * 8]);
#pragma unroll
                for (int u = 0; u < 8; u++) {
                    float g[8];
                    h8_to_f8(rr[u], g);
#pragma unroll
                    for (int q = 0; q < 8; q++) acc[q] += g[q] * wv[u];
                }
            }
#pragma unroll 1
            for (; t + 4 <= cnt; t += 4) {
                int av[4]; float wv[4];
#pragma unroll
                for (int u = 0; u < 4; u++) {
                    av[u] = __shfl_sync(gmask, sj, t + u, 16);
                    wv[u] = __shfl_sync(gmask, wj, t + u, 16);
                }
                uint4 rr[4];
#pragma unroll
                for (int u = 0; u < 4; u++)
                    rr[u] = *reinterpret_cast<const uint4*>(&g_bufH[(size_t)av[u] * 128 + lg * 8]);
#pragma unroll
                for (int u = 0; u < 4; u++) {
                    float g[8];
                    h8_to_f8(rr[u], g);
#pragma unroll
                    for (int q = 0; q < 8; q++) acc[q] += g[q] * wv[u];
                }
            }
#pragma unroll 1
            for (; t < cnt; t++) {
                int s = __shfl_sync(gmask, sj, t, 16);
                float w = __shfl_sync(gmask, wj, t, 16);
                uint4 rv = *reinterpret_cast<const uint4*>(&g_bufH[(size_t)s * 128 + lg * 8]);
                float g[8];
                h8_to_f8(rv, g);
#pragma unroll
                for (int q = 0; q < 8; q++) acc[q] += g[q] * w;
            }
        }
        uint4 outv;
        *reinterpret_cast<__half2*>(&outv.x) = __float22half2_rn(make_float2(acc[0], acc[1]));
        *reinterpret_cast<__half2*>(&outv.y) = __float22half2_rn(make_float2(acc[2], acc[3]));
        *reinterpret_cast<__half2*>(&outv.z) = __float22half2_rn(make_float2(acc[4], acc[5]));
        *reinterpret_cast<__half2*>(&outv.w) = __float22half2_rn(make_float2(acc[6], acc[7]));
        *reinterpret_cast<uint4*>(&g_bufBh[(size_t)n * 128 + lg * 8]) = outv;

#pragma unroll
        for (int q = 0; q < 8; q++) { ps[q] += acc[q]; pq[q] += acc[q] * acc[q]; }
    }

    // cross-group combine (post-reconvergence), then block reduce
#pragma unroll
    for (int q = 0; q < 8; q++) {
        ps[q] += __shfl_xor_sync(0xffffffffu, ps[q], 16);
        pq[q] += __shfl_xor_sync(0xffffffffu, pq[q], 16);
    }
    if (grp == 0) {
#pragma unroll
        for (int q = 0; q < 8; q++) sred[wloc * 128 + lg * 8 + q] = ps[q];
    }
    __syncthreads();
    if (threadIdx.x < 128) {
        float tsum = 0.f;
        for (int ww = 0; ww < 8; ww++) tsum += sred[ww * 128 + threadIdx.x];
        atomicAdd(&g_bnsum[layer * FDIM + threadIdx.x], tsum);
    }
    __syncthreads();
    if (grp == 0) {
#pragma unroll
        for (int q = 0; q < 8; q++) sred[wloc * 128 + lg * 8 + q] = pq[q];
    }
    __syncthreads();
    if (threadIdx.x < 128) {
        float tsq = 0.f;
        for (int ww = 0; ww < 8; ww++) tsq += sred[ww * 128 + threadIdx.x];
        atomicAdd(&g_bnsq[layer * FDIM + threadIdx.x], tsq);
    }
}

// ---------------------------------- Pool -------------------------------------
__global__ void pool_kernel(const int* __restrict__ batch,
                            const float* __restrict__ gamma,
                            const float* __restrict__ beta) {
    int c = threadIdx.x;
    float invN = 1.0f / (float)N_NODES;
    float mean = g_bnsum[2 * FDIM + c] * invN;
    float var = g_bnsq[2 * FDIM + c] * invN - mean * mean;
    float scale = rsqrtf(var + BN_EPS) * gamma[c];
    float shift = beta[c] - mean * scale;

    int start = blockIdx.x * POOL_CHUNK;
    int end = start + POOL_CHUNK; if (end > N_NODES) end = N_NODES;
    if (start >= end) return;
    float acc = 0.f;
    int cur = batch[start];
    int cnt = 0;
    for (int r = start; r < end; r++) {
        int g = batch[r];
        if (g != cur) {
            atomicAdd(&g_pool[cur * FDIM + c], acc);
            if (c == 0) atomicAdd(&g_cnt[cur], (float)cnt);
            acc = 0.f; cnt = 0; cur = g;
        }
        float v = __half2float(g_bufBh[(size_t)r * 128 + c]);
        acc += fmaxf(v * scale + shift, 0.f);
        cnt++;
    }
    atomicAdd(&g_pool[cur * FDIM + c], acc);
    if (c == 0) atomicAdd(&g_cnt[cur], (float)cnt);
}

// -------------------------------- Classifier ---------------------------------
__global__ void classify_kernel(const float* __restrict__ lw1, const float* __restrict__ lb1,
                                const float* __restrict__ lw2, const float* __restrict__ lb2,
                                float* __restrict__ out) {
    __shared__ float p[FDIM], h[FDIM], lo[N_CLASSES];
    int g = blockIdx.x;
    int c = threadIdx.x;
    float cv = fmaxf(g_cnt[g], 1.0f);
    p[c] = g_pool[g * FDIM + c] / cv;
    __syncthreads();
    float a = lb1[c];
    for (int k = 0; k < FDIM; k++) a += p[k] * lw1[k * FDIM + c];
    h[c] = fmaxf(a, 0.f);
    __syncthreads();
    if (c < N_CLASSES) {
        float a2 = lb2[c];
        for (int k = 0; k < FDIM; k++) a2 += h[k] * lw2[k * N_CLASSES + c];
        lo[c] = a2;
    }
    __syncthreads();
    if (c == 0) {
        float m = lo[0];
        for (int j = 1; j < N_CLASSES; j++) m = fmaxf(m, lo[j]);
        float s = 0.f;
        for (int j = 0; j < N_CLASSES; j++) s += expf(lo[j] - m);
        float L = m + logf(s);
        for (int j = 0; j < N_CLASSES; j++) out[g * N_CLASSES + j] = lo[j] - L;
    }
}

// --------------------------------- launch ------------------------------------
extern "C" void kernel_launch(void* const* d_in, const int* in_sizes, int n_in,
                              void* d_out, int out_size) {
    const float* x = (const float*)d_in[0];
    const int* ei = (const int*)d_in[1];
    const int* src = ei;
    const int* dst = ei + N_EDGES;
    const int* batch = (const int*)d_in[2];
    const float* W[3]     = { (const float*)d_in[3], (const float*)d_in[7],  (const float*)d_in[11] };
    const float* b[3]     = { (const float*)d_in[4], (const float*)d_in[8],  (const float*)d_in[12] };
    const float* gamma[3] = { (const float*)d_in[5], (const float*)d_in[9],  (const float*)d_in[13] };
    const float* beta[3]  = { (const float*)d_in[6], (const float*)d_in[10], (const float*)d_in[14] };
    const float* lin1_w = (const float*)d_in[15];
    const float* lin1_b = (const float*)d_in[16];
    const float* lin2_w = (const float*)d_in[17];
    const float* lin2_b = (const float*)d_in[18];
    float* out = (float*)d_out;

    const int smem_gemm = 2 * 128 * XPAD * sizeof(__half);   // 69632 B
    cudaFuncSetAttribute(gemm_kernel, cudaFuncAttributeMaxDynamicSharedMemorySize, smem_gemm);

    int gemm_blocks = (N_NODES + 127) / 128;   // 782

    zero_kernel<<<224, 256>>>();                                     // 0
    hist_kernel<<<(N_EDGES + 255) / 256, 256>>>(dst);                // 1
    wconv_kernel<<<(3 * FDIM * FDIM + 255) / 256, 256>>>(W[0], W[1], W[2]); // 2
    gemm_kernel<<<gemm_blocks, 256, smem_gemm>>>(x, 0, -1, nullptr, nullptr); // 3 (profiled)
    scanA_kernel<<<NB_SCAN, SCAN_CHUNK>>>();                         // 4
    scanB_kernel<<<1, 1>>>();                                        // 5
    scanC_kernel<<<NB_SCAN, SCAN_CHUNK>>>();                         // 6
    fill_kernel<<<(N_EDGES + 255) / 256, 256>>>(src, dst);           // 7
    spmm_kernel<<<1184, 256>>>(b[0], 0);                             // 8
    gemm_kernel<<<gemm_blocks, 256, smem_gemm>>>(nullptr, 1, 0, gamma[0], beta[0]); // 9
    spmm_kernel<<<1184, 256>>>(b[1], 1);                             // 10
    gemm_kernel<<<gemm_blocks, 256, smem_gemm>>>(nullptr, 2, 1, gamma[1], beta[1]); // 11
    spmm_kernel<<<1184, 256>>>(b[2], 2);                             // 12
    pool_kernel<<<NB_POOL, 128>>>(batch, gamma[2], beta[2]);         // 13
    classify_kernel<<<N_GRAPHS, 128>>>(lin1_w, lin1_b, lin2_w, lin2_b, out); // 14
}